// round 1
// baseline (speedup 1.0000x reference)
#include <cuda_runtime.h>
#include <cuda_bf16.h>
#include <math_constants.h>
#include <cstdint>

// Problem constants
#define NB    256       // graphs per batch
#define NPG   512       // nodes per data graph
#define NGN   131072    // total data-graph nodes
#define EGE   1048576   // total data-graph edges
#define NQPG  16        // nodes per query graph
#define NQN   4096      // total query nodes
#define EQE   32768     // total query edges
#define FIN   64
#define HD    128
#define NL    2
#define D2    256       // 2*H

// ---------------- device scratch (no allocs allowed) ----------------
__device__ float d_hg[NGN * HD];        // 64MB
__device__ float d_hqA[NQN * HD];
__device__ float d_hqB[NQN * HD];
__device__ float d_invq[NQN];
__device__ float d_eq[EQE];
__device__ float d_hqaggr[NB * HD];
__device__ float d_cat[NGN * D2];       // 128MB
__device__ float d_invg[NGN];
__device__ float d_eg[EGE];             // 4MB
__device__ float d_agg[NGN * D2];       // 128MB
__device__ float d_t1[NGN * HD];        // 64MB
__device__ float d_hgsum[NB * HD];
__device__ int   d_csrg[EGE];
__device__ int   d_startg[NGN];
__device__ int   d_cntg[NGN];
__device__ int   d_csrq[EQE];
__device__ int   d_startq[NQN];
__device__ int   d_cntq[NQN];

// ---------------- CSR build: deterministic per-graph scan ----------------
// edges are grouped by graph: graph g owns edges [g*EPG, (g+1)*EPG)
template<int NPGT, int EPGT>
__global__ void build_csr_kernel(const int* __restrict__ dst,
                                 int* __restrict__ csr,
                                 int* __restrict__ start,
                                 int* __restrict__ cnt)
{
    __shared__ int sdst[EPGT];
    __shared__ int soff[NPGT];
    int g = blockIdx.x;
    int nodebase = g * NPGT;
    int edgebase = g * EPGT;
    for (int i = threadIdx.x; i < EPGT; i += blockDim.x)
        sdst[i] = dst[edgebase + i] - nodebase;
    __syncthreads();
    int t = threadIdx.x;
    int deg = 0;
    if (t < NPGT) {
        for (int i = 0; i < EPGT; i++) deg += (sdst[i] == t);
        soff[t] = deg;
    }
    __syncthreads();
    if (t == 0) {
        int run = 0;
        for (int i = 0; i < NPGT; i++) { int d0 = soff[i]; soff[i] = run; run += d0; }
    }
    __syncthreads();
    if (t < NPGT) {
        int p = edgebase + soff[t];
        start[nodebase + t] = p;
        cnt[nodebase + t]   = deg;
        for (int i = 0; i < EPGT; i++)
            if (sdst[i] == t) csr[p++] = edgebase + i;   // ascending edge order: deterministic
    }
}

// ---------------- tiled SGEMM: C[M,N] = A[M,K] @ W[K,N] + bias, opt. relu ----------------
// BM=64, BN=64, BK=16, 256 threads, 4x4 per thread. M%64==0, N%64==0, K%16==0.
__global__ void sgemm_bias(const float* __restrict__ A, const float* __restrict__ W,
                           const float* __restrict__ bias, float* __restrict__ C,
                           int M, int N, int K, int do_relu)
{
    __shared__ float As[16][64];
    __shared__ float Bs[16][64];
    int tid = threadIdx.x;
    int tx = tid & 15, ty = tid >> 4;
    int row0 = blockIdx.y * 64, col0 = blockIdx.x * 64;
    float acc[4][4] = {};
    for (int k0 = 0; k0 < K; k0 += 16) {
        #pragma unroll
        for (int idx = tid; idx < 64 * 16; idx += 256) {
            int m = idx >> 4, kk = idx & 15;
            As[kk][m] = A[(size_t)(row0 + m) * K + k0 + kk];
        }
        #pragma unroll
        for (int idx = tid; idx < 16 * 64; idx += 256) {
            int kk = idx >> 6, n = idx & 63;
            Bs[kk][n] = W[(size_t)(k0 + kk) * N + col0 + n];
        }
        __syncthreads();
        #pragma unroll
        for (int kk = 0; kk < 16; kk++) {
            float a[4], b[4];
            #pragma unroll
            for (int i = 0; i < 4; i++) a[i] = As[kk][ty * 4 + i];
            #pragma unroll
            for (int j = 0; j < 4; j++) b[j] = Bs[kk][tx * 4 + j];
            #pragma unroll
            for (int i = 0; i < 4; i++)
                #pragma unroll
                for (int j = 0; j < 4; j++)
                    acc[i][j] += a[i] * b[j];
        }
        __syncthreads();
    }
    #pragma unroll
    for (int i = 0; i < 4; i++) {
        int r = row0 + ty * 4 + i;
        #pragma unroll
        for (int j = 0; j < 4; j++) {
            int c = col0 + tx * 4 + j;
            float v = acc[i][j] + bias[c];
            if (do_relu) v = fmaxf(v, 0.0f);
            C[(size_t)r * N + c] = v;
        }
    }
}

// ---------------- per-row inverse norm: inv[i] = rsqrt(sum(h_i^2) + 1e-24) ----------------
template<int D>
__global__ void row_inv_norm(const float* __restrict__ h, float* __restrict__ inv, int N)
{
    int w = (blockIdx.x * blockDim.x + threadIdx.x) >> 5;
    int lane = threadIdx.x & 31;
    if (w >= N) return;
    const float4* hr = (const float4*)(h + (size_t)w * D);
    float ss = 0.0f;
    #pragma unroll
    for (int c = 0; c < D / 128; c++) {
        float4 a = hr[lane + 32 * c];
        ss += a.x * a.x + a.y * a.y + a.z * a.z + a.w * a.w;
    }
    #pragma unroll
    for (int o = 16; o; o >>= 1) ss += __shfl_xor_sync(0xFFFFFFFFu, ss, o);
    if (lane == 0) inv[w] = rsqrtf(ss + 1e-24f);
}

// ---------------- edge logits: e = beta * inv_s * inv_d * dot(h_s, h_d) ----------------
template<int D>
__global__ void edge_logits(const float* __restrict__ h, const float* __restrict__ inv,
                            const int* __restrict__ src, const int* __restrict__ dst,
                            const float* __restrict__ betas, int l,
                            float* __restrict__ e, int E)
{
    int w = (blockIdx.x * blockDim.x + threadIdx.x) >> 5;
    int lane = threadIdx.x & 31;
    if (w >= E) return;
    int s = src[w], d = dst[w];
    const float4* hs = (const float4*)(h + (size_t)s * D);
    const float4* hd = (const float4*)(h + (size_t)d * D);
    float dot = 0.0f;
    #pragma unroll
    for (int c = 0; c < D / 128; c++) {
        float4 a = hs[lane + 32 * c];
        float4 b = hd[lane + 32 * c];
        dot += a.x * b.x + a.y * b.y + a.z * b.z + a.w * b.w;
    }
    #pragma unroll
    for (int o = 16; o; o >>= 1) dot += __shfl_xor_sync(0xFFFFFFFFu, dot, o);
    if (lane == 0) e[w] = betas[l] * inv[s] * inv[d] * dot;
}

// ---------------- AGNN gather: softmax over in-edges + weighted sum (warp/node) ----------------
template<int D>
__global__ void agnn_aggregate(const float* __restrict__ h, const float* __restrict__ e,
                               const int* __restrict__ csr, const int* __restrict__ start,
                               const int* __restrict__ cnt, const int* __restrict__ src,
                               float* __restrict__ out, int N)
{
    int n = (blockIdx.x * blockDim.x + threadIdx.x) >> 5;
    int lane = threadIdx.x & 31;
    if (n >= N) return;
    int s0 = start[n];
    int c  = cnt[n];
    float4 acc[D / 128];
    #pragma unroll
    for (int k = 0; k < D / 128; k++) acc[k] = make_float4(0.f, 0.f, 0.f, 0.f);

    if (c > 0) {
        float m = -CUDART_INF_F;
        for (int j = 0; j < c; j++) m = fmaxf(m, e[csr[s0 + j]]);   // broadcast loads
        float den = 0.0f;
        for (int j = 0; j < c; j++) {
            int eid = csr[s0 + j];
            float ee = expf(e[eid] - m);
            den += ee;
            const float4* hs = (const float4*)(h + (size_t)src[eid] * D);
            #pragma unroll
            for (int k = 0; k < D / 128; k++) {
                float4 a = hs[lane + 32 * k];
                acc[k].x += ee * a.x; acc[k].y += ee * a.y;
                acc[k].z += ee * a.z; acc[k].w += ee * a.w;
            }
        }
        float r = 1.0f / fmaxf(den, 1e-24f);
        #pragma unroll
        for (int k = 0; k < D / 128; k++) {
            acc[k].x *= r; acc[k].y *= r; acc[k].z *= r; acc[k].w *= r;
        }
    }
    float4* orow = (float4*)(out + (size_t)n * D);
    #pragma unroll
    for (int k = 0; k < D / 128; k++) orow[lane + 32 * k] = acc[k];
}

// ---------------- per-graph sum pool over H=128 feature columns ----------------
__global__ void pool_sum(const float* __restrict__ h, float* __restrict__ out, int per_graph)
{
    int g = blockIdx.x, t = threadIdx.x;   // 128 threads
    float s = 0.0f;
    const float* base = h + (size_t)g * per_graph * HD + t;
    for (int j = 0; j < per_graph; j++) s += base[(size_t)j * HD];
    out[g * HD + t] = s;
}

// ---------------- concat: cat[i] = [h_g[i], hq_aggr[i/512]] ----------------
__global__ void build_cat(const float* __restrict__ hg, const float* __restrict__ aggr,
                          float* __restrict__ cat)
{
    int i = blockIdx.x * blockDim.x + threadIdx.x;   // over NGN*64 float4s
    int node = i >> 6, c4 = i & 63;
    float4 v = (c4 < 32) ? ((const float4*)hg)[node * 32 + c4]
                         : ((const float4*)aggr)[(node >> 9) * 32 + (c4 - 32)];
    ((float4*)cat)[i] = v;
}

// ---------------- final predictor: y = relu(hgsum@Wp1+bp1)@Wp2+bp2 ----------------
__global__ void predictor(const float* __restrict__ hgsum, const float* __restrict__ Wp1,
                          const float* __restrict__ bp1, const float* __restrict__ Wp2,
                          const float* __restrict__ bp2, float* __restrict__ y)
{
    __shared__ float srow[HD];
    __shared__ float st[HD];
    int g = blockIdx.x, t = threadIdx.x;   // 128 threads
    srow[t] = hgsum[g * HD + t];
    __syncthreads();
    float a = 0.0f;
    #pragma unroll 8
    for (int k = 0; k < HD; k++) a += srow[k] * Wp1[k * HD + t];
    st[t] = fmaxf(a + bp1[t], 0.0f) * Wp2[t];
    __syncthreads();
    #pragma unroll
    for (int s = 64; s; s >>= 1) {
        if (t < s) st[t] += st[t + s];
        __syncthreads();
    }
    if (t == 0) y[g] = st[0] + bp2[0];
}

// ---------------- launch ----------------
extern "C" void kernel_launch(void* const* d_in, const int* in_sizes, int n_in,
                              void* d_out, int out_size)
{
    const float* X     = (const float*)d_in[0];
    const float* Xq    = (const float*)d_in[1];
    const int*   g_src = (const int*)d_in[2];
    const int*   g_dst = (const int*)d_in[3];
    // d_in[4] = g_n2g (implicit: node/512)
    const int*   q_src = (const int*)d_in[5];
    const int*   q_dst = (const int*)d_in[6];
    // d_in[7] = q_n2g (implicit: node/16)
    const float* Wg    = (const float*)d_in[8];
    const float* bg    = (const float*)d_in[9];
    const float* Wq    = (const float*)d_in[10];
    const float* bq    = (const float*)d_in[11];
    const float* betas_g = (const float*)d_in[12];
    const float* betas_q = (const float*)d_in[13];
    const float* W1r   = (const float*)d_in[14];
    const float* b1r   = (const float*)d_in[15];
    const float* W2r   = (const float*)d_in[16];
    const float* b2r   = (const float*)d_in[17];
    const float* Wp1   = (const float*)d_in[18];
    const float* bp1   = (const float*)d_in[19];
    const float* Wp2   = (const float*)d_in[20];
    const float* bp2   = (const float*)d_in[21];
    float* y = (float*)d_out;

    float *hg, *hqA, *hqB, *invq, *eq, *hqaggr, *cat, *invg, *eg, *agg, *t1, *hgsum;
    int *csrg, *startg, *cntg, *csrq, *startq, *cntq;
    cudaGetSymbolAddress((void**)&hg, d_hg);
    cudaGetSymbolAddress((void**)&hqA, d_hqA);
    cudaGetSymbolAddress((void**)&hqB, d_hqB);
    cudaGetSymbolAddress((void**)&invq, d_invq);
    cudaGetSymbolAddress((void**)&eq, d_eq);
    cudaGetSymbolAddress((void**)&hqaggr, d_hqaggr);
    cudaGetSymbolAddress((void**)&cat, d_cat);
    cudaGetSymbolAddress((void**)&invg, d_invg);
    cudaGetSymbolAddress((void**)&eg, d_eg);
    cudaGetSymbolAddress((void**)&agg, d_agg);
    cudaGetSymbolAddress((void**)&t1, d_t1);
    cudaGetSymbolAddress((void**)&hgsum, d_hgsum);
    cudaGetSymbolAddress((void**)&csrg, d_csrg);
    cudaGetSymbolAddress((void**)&startg, d_startg);
    cudaGetSymbolAddress((void**)&cntg, d_cntg);
    cudaGetSymbolAddress((void**)&csrq, d_csrq);
    cudaGetSymbolAddress((void**)&startq, d_startq);
    cudaGetSymbolAddress((void**)&cntq, d_cntq);

    // CSR build (constant across layers)
    build_csr_kernel<NPG, EGE / NB><<<NB, 512>>>(g_dst, csrg, startg, cntg);
    build_csr_kernel<NQPG, EQE / NB><<<NB, 128>>>(q_dst, csrq, startq, cntq);

    // input projections
    sgemm_bias<<<dim3(HD / 64, NGN / 64), 256>>>(X, Wg, bg, hg, NGN, HD, FIN, 0);
    sgemm_bias<<<dim3(HD / 64, NQN / 64), 256>>>(Xq, Wq, bq, hqA, NQN, HD, FIN, 0);

    float* hq_cur = hqA;
    float* hq_nxt = hqB;
    for (int l = 0; l < NL; l++) {
        // --- query AGNN ---
        row_inv_norm<HD><<<NQN / 8, 256>>>(hq_cur, invq, NQN);
        edge_logits<HD><<<EQE / 8, 256>>>(hq_cur, invq, q_src, q_dst, betas_q, l, eq, EQE);
        agnn_aggregate<HD><<<NQN / 8, 256>>>(hq_cur, eq, csrq, startq, cntq, q_src, hq_nxt, NQN);
        // --- per-graph query aggregation + concat ---
        pool_sum<<<NB, 128>>>(hq_nxt, hqaggr, NQPG);
        build_cat<<<NGN * 64 / 256, 256>>>(hg, hqaggr, cat);
        // --- data-graph AGNN on [NGN, 256] ---
        row_inv_norm<D2><<<NGN / 8, 256>>>(cat, invg, NGN);
        edge_logits<D2><<<EGE / 8, 256>>>(cat, invg, g_src, g_dst, betas_g, l, eg, EGE);
        agnn_aggregate<D2><<<NGN / 8, 256>>>(cat, eg, csrg, startg, cntg, g_src, agg, NGN);
        // --- MLP reduce ---
        sgemm_bias<<<dim3(HD / 64, NGN / 64), 256>>>(agg, W1r + (size_t)l * D2 * HD,
                                                     b1r + l * HD, t1, NGN, HD, D2, 1);
        sgemm_bias<<<dim3(HD / 64, NGN / 64), 256>>>(t1, W2r + (size_t)l * HD * HD,
                                                     b2r + l * HD, hg, NGN, HD, HD, 0);
        // swap query ping-pong
        float* tmp = hq_cur; hq_cur = hq_nxt; hq_nxt = tmp;
    }

    // final pooling + predictor
    pool_sum<<<NB, 128>>>(hg, hgsum, NPG);
    predictor<<<NB, 128>>>(hgsum, Wp1, bp1, Wp2, bp2, y);
}

// round 2
// speedup vs baseline: 1.8924x; 1.8924x over previous
#include <cuda_runtime.h>
#include <cuda_bf16.h>
#include <math_constants.h>
#include <cstdint>

// Problem constants
#define NB    256
#define NPG   512
#define NGN   131072
#define EGE   1048576
#define NQPG  16
#define NQN   4096
#define EQE   32768
#define FIN   64
#define HD    128
#define NL    2

// ---------------- device scratch ----------------
__device__ float d_hg[NGN * HD];
__device__ float d_hqA[NQN * HD];
__device__ float d_hqB[NQN * HD];
__device__ float d_ssqq[NQN];
__device__ float d_eq[EQE];
__device__ float d_hqaggr[NB * HD];
__device__ float d_ssqa[NB];
__device__ float d_vg[NB * HD];
__device__ float d_ssqg[NGN];
__device__ float d_eg[EGE];
__device__ float d_aggP[NGN * HD];
__device__ float d_t1[NGN * HD];
__device__ float d_hgsum[NB * HD];
__device__ int   d_csrg[EGE];
__device__ int   d_startg[NGN];
__device__ int   d_cntg[NGN];
__device__ int   d_csrq[EQE];
__device__ int   d_startq[NQN];
__device__ int   d_cntq[NQN];

// ---------------- CSR build (deterministic per-graph scan) ----------------
template<int NPGT, int EPGT>
__global__ void build_csr_kernel(const int* __restrict__ dst,
                                 int* __restrict__ csr,
                                 int* __restrict__ start,
                                 int* __restrict__ cnt)
{
    __shared__ int sdst[EPGT];
    __shared__ int soff[NPGT];
    int g = blockIdx.x;
    int nodebase = g * NPGT;
    int edgebase = g * EPGT;
    for (int i = threadIdx.x; i < EPGT; i += blockDim.x)
        sdst[i] = dst[edgebase + i] - nodebase;
    __syncthreads();
    int t = threadIdx.x;
    int deg = 0;
    if (t < NPGT) {
        for (int i = 0; i < EPGT; i++) deg += (sdst[i] == t);
        soff[t] = deg;
    }
    __syncthreads();
    if (t == 0) {
        int run = 0;
        for (int i = 0; i < NPGT; i++) { int d0 = soff[i]; soff[i] = run; run += d0; }
    }
    __syncthreads();
    if (t < NPGT) {
        int p = edgebase + soff[t];
        start[nodebase + t] = p;
        cnt[nodebase + t]   = deg;
        for (int i = 0; i < EPGT; i++)
            if (sdst[i] == t) csr[p++] = edgebase + i;
    }
}

// ---------------- split-bf16 tensor-core GEMM ----------------
// C[M,128] = A[M,K] @ W[K,128] + bias  [+ relu] [+ (cnt[row]>0 ? vg[row>>9] : 0)]
// Block: 128 rows x 128 cols, 256 threads (8 warps: warp_m = wid>>1 (4), warp_n = wid&1 (2)).
// a = ah + al (bf16 split); C += ah*bh + ah*bl + al*bh  (fp32 accum, err ~2^-16)

__device__ __forceinline__ uint32_t sptr(const void* p) {
    return (uint32_t)__cvta_generic_to_shared(p);
}
__device__ __forceinline__ void ldsm4(uint32_t& r0, uint32_t& r1, uint32_t& r2, uint32_t& r3, uint32_t a) {
    asm volatile("ldmatrix.sync.aligned.m8n8.x4.shared.b16 {%0,%1,%2,%3},[%4];\n"
                 : "=r"(r0), "=r"(r1), "=r"(r2), "=r"(r3) : "r"(a));
}
__device__ __forceinline__ void ldsm4t(uint32_t& r0, uint32_t& r1, uint32_t& r2, uint32_t& r3, uint32_t a) {
    asm volatile("ldmatrix.sync.aligned.m8n8.x4.trans.shared.b16 {%0,%1,%2,%3},[%4];\n"
                 : "=r"(r0), "=r"(r1), "=r"(r2), "=r"(r3) : "r"(a));
}
__device__ __forceinline__ void mma16816(float* c, const uint32_t* a, uint32_t b0, uint32_t b1) {
    asm volatile("mma.sync.aligned.m16n8k16.row.col.f32.bf16.bf16.f32 "
                 "{%0,%1,%2,%3},{%4,%5,%6,%7},{%8,%9},{%0,%1,%2,%3};\n"
                 : "+f"(c[0]), "+f"(c[1]), "+f"(c[2]), "+f"(c[3])
                 : "r"(a[0]), "r"(a[1]), "r"(a[2]), "r"(a[3]), "r"(b0), "r"(b1));
}

template<int K>
__global__ __launch_bounds__(256) void gemm_mma(
    const float* __restrict__ A, const float* __restrict__ W,
    const float* __restrict__ bias, float* __restrict__ C,
    const float* __restrict__ vg, const int* __restrict__ cnt, int do_relu)
{
    __shared__ __align__(16) __nv_bfloat16 sAh[128][40];
    __shared__ __align__(16) __nv_bfloat16 sAl[128][40];
    __shared__ __align__(16) __nv_bfloat16 sBh[32][136];
    __shared__ __align__(16) __nv_bfloat16 sBl[32][136];

    int tid = threadIdx.x;
    int wid = tid >> 5, lane = tid & 31;
    int warp_m = wid >> 1, warp_n = wid & 1;
    int row0 = blockIdx.x * 128;

    float acc[2][8][4];
    #pragma unroll
    for (int i = 0; i < 2; i++)
        #pragma unroll
        for (int j = 0; j < 8; j++)
            #pragma unroll
            for (int k = 0; k < 4; k++) acc[i][j][k] = 0.0f;

    // precompute ldmatrix shared addresses (base offsets vary per k-step)
    for (int k0 = 0; k0 < K; k0 += 32) {
        // load + split A tile [128 x 32]
        #pragma unroll
        for (int it = 0; it < 4; it++) {
            int idx = tid + it * 256;            // 0..1023 float4s
            int m = idx >> 3, f = (idx & 7) * 4;
            float4 v = *(const float4*)(A + (size_t)(row0 + m) * K + k0 + f);
            __nv_bfloat162 h0 = __floats2bfloat162_rn(v.x, v.y);
            __nv_bfloat162 h1 = __floats2bfloat162_rn(v.z, v.w);
            __nv_bfloat162 l0 = __floats2bfloat162_rn(v.x - __bfloat162float(h0.x),
                                                      v.y - __bfloat162float(h0.y));
            __nv_bfloat162 l1 = __floats2bfloat162_rn(v.z - __bfloat162float(h1.x),
                                                      v.w - __bfloat162float(h1.y));
            *(__nv_bfloat162*)&sAh[m][f]     = h0;
            *(__nv_bfloat162*)&sAh[m][f + 2] = h1;
            *(__nv_bfloat162*)&sAl[m][f]     = l0;
            *(__nv_bfloat162*)&sAl[m][f + 2] = l1;
        }
        // load + split B tile [32 x 128]
        #pragma unroll
        for (int it = 0; it < 4; it++) {
            int idx = tid + it * 256;
            int kk = idx >> 5, f = (idx & 31) * 4;
            float4 v = *(const float4*)(W + (size_t)(k0 + kk) * 128 + f);
            __nv_bfloat162 h0 = __floats2bfloat162_rn(v.x, v.y);
            __nv_bfloat162 h1 = __floats2bfloat162_rn(v.z, v.w);
            __nv_bfloat162 l0 = __floats2bfloat162_rn(v.x - __bfloat162float(h0.x),
                                                      v.y - __bfloat162float(h0.y));
            __nv_bfloat162 l1 = __floats2bfloat162_rn(v.z - __bfloat162float(h1.x),
                                                      v.w - __bfloat162float(h1.y));
            *(__nv_bfloat162*)&sBh[kk][f]     = h0;
            *(__nv_bfloat162*)&sBh[kk][f + 2] = h1;
            *(__nv_bfloat162*)&sBl[kk][f]     = l0;
            *(__nv_bfloat162*)&sBl[kk][f + 2] = l1;
        }
        __syncthreads();

        #pragma unroll
        for (int ks = 0; ks < 32; ks += 16) {
            uint32_t ah[2][4], al[2][4];
            #pragma unroll
            for (int mt = 0; mt < 2; mt++) {
                int r = warp_m * 32 + mt * 16 + (lane & 15);
                int c = ks + (lane >> 4) * 8;
                ldsm4(ah[mt][0], ah[mt][1], ah[mt][2], ah[mt][3], sptr(&sAh[r][c]));
                ldsm4(al[mt][0], al[mt][1], al[mt][2], al[mt][3], sptr(&sAl[r][c]));
            }
            #pragma unroll
            for (int np = 0; np < 4; np++) {
                int kk = ks + (lane & 7) + ((lane >> 3) & 1) * 8;
                int cc = warp_n * 64 + np * 16 + (lane >> 4) * 8;
                uint32_t bh[4], bl[4];
                ldsm4t(bh[0], bh[1], bh[2], bh[3], sptr(&sBh[kk][cc]));
                ldsm4t(bl[0], bl[1], bl[2], bl[3], sptr(&sBl[kk][cc]));
                #pragma unroll
                for (int mt = 0; mt < 2; mt++) {
                    #pragma unroll
                    for (int sub = 0; sub < 2; sub++) {
                        float* c0 = acc[mt][np * 2 + sub];
                        mma16816(c0, ah[mt], bh[sub * 2], bh[sub * 2 + 1]);
                        mma16816(c0, ah[mt], bl[sub * 2], bl[sub * 2 + 1]);
                        mma16816(c0, al[mt], bh[sub * 2], bh[sub * 2 + 1]);
                    }
                }
            }
        }
        __syncthreads();
    }

    // epilogue
    #pragma unroll
    for (int mt = 0; mt < 2; mt++) {
        int r0 = row0 + warp_m * 32 + mt * 16 + (lane >> 2);
        #pragma unroll
        for (int nt = 0; nt < 8; nt++) {
            int col = warp_n * 64 + nt * 8 + (lane & 3) * 2;
            float b0 = bias[col], b1 = bias[col + 1];
            float v0 = acc[mt][nt][0] + b0;
            float v1 = acc[mt][nt][1] + b1;
            float v2 = acc[mt][nt][2] + b0;
            float v3 = acc[mt][nt][3] + b1;
            if (vg) {
                int ra = r0, rb = r0 + 8;
                float ma = (cnt[ra] > 0) ? 1.0f : 0.0f;
                float mb = (cnt[rb] > 0) ? 1.0f : 0.0f;
                const float* va = vg + (size_t)(ra >> 9) * HD;
                const float* vb = vg + (size_t)(rb >> 9) * HD;
                v0 += ma * va[col]; v1 += ma * va[col + 1];
                v2 += mb * vb[col]; v3 += mb * vb[col + 1];
            }
            if (do_relu) {
                v0 = fmaxf(v0, 0.f); v1 = fmaxf(v1, 0.f);
                v2 = fmaxf(v2, 0.f); v3 = fmaxf(v3, 0.f);
            }
            *(float2*)(C + (size_t)r0 * 128 + col)       = make_float2(v0, v1);
            *(float2*)(C + (size_t)(r0 + 8) * 128 + col) = make_float2(v2, v3);
        }
    }
}

// ---------------- row sum-of-squares (D=128): ssq[i] = sum(h_i^2) ----------------
__global__ void row_ssq(const float* __restrict__ h, float* __restrict__ ssq, int N)
{
    int w = (blockIdx.x * blockDim.x + threadIdx.x) >> 5;
    int lane = threadIdx.x & 31;
    if (w >= N) return;
    float4 a = ((const float4*)(h + (size_t)w * HD))[lane];
    float ss = a.x * a.x + a.y * a.y + a.z * a.z + a.w * a.w;
    #pragma unroll
    for (int o = 16; o; o >>= 1) ss += __shfl_xor_sync(0xFFFFFFFFu, ss, o);
    if (lane == 0) ssq[w] = ss;
}

// ---------------- edge logits (D=128, optional per-graph extra scalar) ----------------
// e = beta * (dot(h_s,h_d) + extra_g) * rsqrt(ssq_s+extra_g+eps) * rsqrt(ssq_d+extra_g+eps)
__global__ void edge_logits(const float* __restrict__ h, const float* __restrict__ ssq,
                            const int* __restrict__ src, const int* __restrict__ dst,
                            const float* __restrict__ betas, int l,
                            const float* __restrict__ extra, int shift,
                            float* __restrict__ e, int E)
{
    int w = (blockIdx.x * blockDim.x + threadIdx.x) >> 5;
    int lane = threadIdx.x & 31;
    if (w >= E) return;
    int s = src[w], d = dst[w];
    float4 a = ((const float4*)(h + (size_t)s * HD))[lane];
    float4 b = ((const float4*)(h + (size_t)d * HD))[lane];
    float dot = a.x * b.x + a.y * b.y + a.z * b.z + a.w * b.w;
    #pragma unroll
    for (int o = 16; o; o >>= 1) dot += __shfl_xor_sync(0xFFFFFFFFu, dot, o);
    if (lane == 0) {
        float ex = extra ? extra[s >> shift] : 0.0f;
        float invs = rsqrtf(ssq[s] + ex + 1e-24f);
        float invd = rsqrtf(ssq[d] + ex + 1e-24f);
        e[w] = betas[l] * (dot + ex) * invs * invd;
    }
}

// ---------------- AGNN gather (D=128): softmax over in-edges + weighted sum ----------------
__global__ void agnn_aggregate(const float* __restrict__ h, const float* __restrict__ e,
                               const int* __restrict__ csr, const int* __restrict__ start,
                               const int* __restrict__ cnt, const int* __restrict__ src,
                               float* __restrict__ out, int N)
{
    int n = (blockIdx.x * blockDim.x + threadIdx.x) >> 5;
    int lane = threadIdx.x & 31;
    if (n >= N) return;
    int s0 = start[n];
    int c  = cnt[n];
    float4 acc = make_float4(0.f, 0.f, 0.f, 0.f);
    if (c > 0) {
        float m = -CUDART_INF_F;
        for (int j = 0; j < c; j++) m = fmaxf(m, e[csr[s0 + j]]);
        float den = 0.0f;
        for (int j = 0; j < c; j++) {
            int eid = csr[s0 + j];
            float ee = expf(e[eid] - m);
            den += ee;
            float4 a = ((const float4*)(h + (size_t)src[eid] * HD))[lane];
            acc.x += ee * a.x; acc.y += ee * a.y;
            acc.z += ee * a.z; acc.w += ee * a.w;
        }
        float r = 1.0f / fmaxf(den, 1e-24f);
        acc.x *= r; acc.y *= r; acc.z *= r; acc.w *= r;
    }
    ((float4*)(out + (size_t)n * HD))[lane] = acc;
}

// ---------------- per-graph sum pool over H=128 ----------------
__global__ void pool_sum(const float* __restrict__ h, float* __restrict__ out, int per_graph)
{
    int g = blockIdx.x, t = threadIdx.x;   // 128 threads
    float s = 0.0f;
    const float* base = h + (size_t)g * per_graph * HD + t;
    for (int j = 0; j < per_graph; j++) s += base[(size_t)j * HD];
    out[g * HD + t] = s;
}

// ---------------- per-graph ssq of aggr: ssqa[g] = sum(aggr_g^2) ----------------
__global__ void graph_ssq(const float* __restrict__ aggr, float* __restrict__ ssqa)
{
    __shared__ float s[128];
    int g = blockIdx.x, t = threadIdx.x;
    float v = aggr[g * HD + t];
    s[t] = v * v;
    __syncthreads();
    #pragma unroll
    for (int o = 64; o; o >>= 1) {
        if (t < o) s[t] += s[t + o];
        __syncthreads();
    }
    if (t == 0) ssqa[g] = s[0];
}

// ---------------- per-graph v_g = aggr_g @ W1_bot  (tiny GEMM) ----------------
__global__ void vg_gemm(const float* __restrict__ aggr, const float* __restrict__ W1bot,
                        float* __restrict__ vg)
{
    __shared__ float s[128];
    int g = blockIdx.x, t = threadIdx.x;
    s[t] = aggr[g * HD + t];
    __syncthreads();
    float a = 0.0f;
    #pragma unroll 8
    for (int k = 0; k < HD; k++) a += s[k] * W1bot[k * HD + t];
    vg[g * HD + t] = a;
}

// ---------------- final predictor ----------------
__global__ void predictor(const float* __restrict__ hgsum, const float* __restrict__ Wp1,
                          const float* __restrict__ bp1, const float* __restrict__ Wp2,
                          const float* __restrict__ bp2, float* __restrict__ y)
{
    __shared__ float srow[HD];
    __shared__ float st[HD];
    int g = blockIdx.x, t = threadIdx.x;
    srow[t] = hgsum[g * HD + t];
    __syncthreads();
    float a = 0.0f;
    #pragma unroll 8
    for (int k = 0; k < HD; k++) a += srow[k] * Wp1[k * HD + t];
    st[t] = fmaxf(a + bp1[t], 0.0f) * Wp2[t];
    __syncthreads();
    #pragma unroll
    for (int s = 64; s; s >>= 1) {
        if (t < s) st[t] += st[t + s];
        __syncthreads();
    }
    if (t == 0) y[g] = st[0] + bp2[0];
}

// ---------------- launch ----------------
extern "C" void kernel_launch(void* const* d_in, const int* in_sizes, int n_in,
                              void* d_out, int out_size)
{
    const float* X     = (const float*)d_in[0];
    const float* Xq    = (const float*)d_in[1];
    const int*   g_src = (const int*)d_in[2];
    const int*   g_dst = (const int*)d_in[3];
    const int*   q_src = (const int*)d_in[5];
    const int*   q_dst = (const int*)d_in[6];
    const float* Wg    = (const float*)d_in[8];
    const float* bg    = (const float*)d_in[9];
    const float* Wq    = (const float*)d_in[10];
    const float* bq    = (const float*)d_in[11];
    const float* betas_g = (const float*)d_in[12];
    const float* betas_q = (const float*)d_in[13];
    const float* W1r   = (const float*)d_in[14];
    const float* b1r   = (const float*)d_in[15];
    const float* W2r   = (const float*)d_in[16];
    const float* b2r   = (const float*)d_in[17];
    const float* Wp1   = (const float*)d_in[18];
    const float* bp1   = (const float*)d_in[19];
    const float* Wp2   = (const float*)d_in[20];
    const float* bp2   = (const float*)d_in[21];
    float* y = (float*)d_out;

    float *hg, *hqA, *hqB, *ssqq, *eq, *hqaggr, *ssqa, *vg, *ssqg, *eg, *aggP, *t1, *hgsum;
    int *csrg, *startg, *cntg, *csrq, *startq, *cntq;
    cudaGetSymbolAddress((void**)&hg, d_hg);
    cudaGetSymbolAddress((void**)&hqA, d_hqA);
    cudaGetSymbolAddress((void**)&hqB, d_hqB);
    cudaGetSymbolAddress((void**)&ssqq, d_ssqq);
    cudaGetSymbolAddress((void**)&eq, d_eq);
    cudaGetSymbolAddress((void**)&hqaggr, d_hqaggr);
    cudaGetSymbolAddress((void**)&ssqa, d_ssqa);
    cudaGetSymbolAddress((void**)&vg, d_vg);
    cudaGetSymbolAddress((void**)&ssqg, d_ssqg);
    cudaGetSymbolAddress((void**)&eg, d_eg);
    cudaGetSymbolAddress((void**)&aggP, d_aggP);
    cudaGetSymbolAddress((void**)&t1, d_t1);
    cudaGetSymbolAddress((void**)&hgsum, d_hgsum);
    cudaGetSymbolAddress((void**)&csrg, d_csrg);
    cudaGetSymbolAddress((void**)&startg, d_startg);
    cudaGetSymbolAddress((void**)&cntg, d_cntg);
    cudaGetSymbolAddress((void**)&csrq, d_csrq);
    cudaGetSymbolAddress((void**)&startq, d_startq);
    cudaGetSymbolAddress((void**)&cntq, d_cntq);

    build_csr_kernel<NPG, EGE / NB><<<NB, 512>>>(g_dst, csrg, startg, cntg);
    build_csr_kernel<NQPG, EQE / NB><<<NB, 128>>>(q_dst, csrq, startq, cntq);

    // input projections (tensor core)
    gemm_mma<FIN><<<NGN / 128, 256>>>(X, Wg, bg, hg, nullptr, nullptr, 0);
    gemm_mma<FIN><<<NQN / 128, 256>>>(Xq, Wq, bq, hqA, nullptr, nullptr, 0);

    float* hq_cur = hqA;
    float* hq_nxt = hqB;
    for (int l = 0; l < NL; l++) {
        // --- query AGNN (128-dim) ---
        row_ssq<<<NQN / 8, 256>>>(hq_cur, ssqq, NQN);
        edge_logits<<<EQE / 8, 256>>>(hq_cur, ssqq, q_src, q_dst, betas_q, l,
                                      nullptr, 0, eq, EQE);
        agnn_aggregate<<<NQN / 8, 256>>>(hq_cur, eq, csrq, startq, cntq, q_src, hq_nxt, NQN);
        // --- per-graph query pooling + derived scalars ---
        pool_sum<<<NB, 128>>>(hq_nxt, hqaggr, NQPG);
        graph_ssq<<<NB, 128>>>(hqaggr, ssqa);
        vg_gemm<<<NB, 128>>>(hqaggr, W1r + (size_t)l * 2 * HD * HD + HD * HD, vg);
        // --- data-graph AGNN, concat folded out (128-dim + per-graph scalar) ---
        row_ssq<<<NGN / 8, 256>>>(hg, ssqg, NGN);
        edge_logits<<<EGE / 8, 256>>>(hg, ssqg, g_src, g_dst, betas_g, l,
                                      ssqa, 9, eg, EGE);
        agnn_aggregate<<<NGN / 8, 256>>>(hg, eg, csrg, startg, cntg, g_src, aggP, NGN);
        // --- MLP reduce: relu(aggP@W1top + mask*vg + b1) @ W2 + b2 ---
        gemm_mma<HD><<<NGN / 128, 256>>>(aggP, W1r + (size_t)l * 2 * HD * HD,
                                         b1r + l * HD, t1, vg, cntg, 1);
        gemm_mma<HD><<<NGN / 128, 256>>>(t1, W2r + (size_t)l * HD * HD,
                                         b2r + l * HD, hg, nullptr, nullptr, 0);
        float* tmp = hq_cur; hq_cur = hq_nxt; hq_nxt = tmp;
    }

    pool_sum<<<NB, 128>>>(hg, hgsum, NPG);
    predictor<<<NB, 128>>>(hgsum, Wp1, bp1, Wp2, bp2, y);
}

// round 3
// speedup vs baseline: 2.1087x; 1.1143x over previous
#include <cuda_runtime.h>
#include <cuda_bf16.h>
#include <math_constants.h>
#include <cstdint>

#define NB    256
#define NPG   512
#define NGN   131072
#define EGE   1048576
#define NQPG  16
#define NQN   4096
#define EQE   32768
#define FIN   64
#define HD    128
#define NL    2

typedef __nv_bfloat16 bf16;
typedef __nv_bfloat162 bf162;

// ---------------- device scratch ----------------
__device__ __align__(16) float d_hg[NGN * HD];
__device__ __align__(16) float d_hqA[NQN * HD];
__device__ __align__(16) float d_hqB[NQN * HD];
__device__ float d_ssqq[NQN];
__device__ float d_ssqg[NGN];
__device__ float d_ssqa[NB];
__device__ float d_hqaggr[NB * HD];
__device__ float d_vg[NB * HD];
__device__ float d_hgsum[NB * HD];
__device__ __align__(16) bf16 d_Xh[NGN * FIN];
__device__ __align__(16) bf16 d_Xl[NGN * FIN];
__device__ __align__(16) bf16 d_Xqh[NQN * FIN];
__device__ __align__(16) bf16 d_Xql[NQN * FIN];
__device__ __align__(16) bf16 d_Wh[6 * HD * HD];
__device__ __align__(16) bf16 d_Wl[6 * HD * HD];
__device__ __align__(16) bf16 d_aggh[NGN * HD];
__device__ __align__(16) bf16 d_aggl[NGN * HD];
__device__ __align__(16) bf16 d_t1h[NGN * HD];
__device__ __align__(16) bf16 d_t1l[NGN * HD];
__device__ int d_csrg[EGE];
__device__ int d_startg[NGN];
__device__ int d_cntg[NGN];
__device__ int d_csrq[EQE];
__device__ int d_startq[NQN];
__device__ int d_cntq[NQN];

// ---------------- O(E) deterministic CSR build ----------------
// warp-private histograms + stable ballot-ranked fill: csr order = ascending edge id.
template<int NPGT, int EPGT, int W>
__global__ void build_csr2(const int* __restrict__ dst,
                           int* __restrict__ csr,
                           int* __restrict__ start,
                           int* __restrict__ cnt)
{
    __shared__ int hw[W][NPGT];
    __shared__ int soff[NPGT];
    const int g = blockIdx.x;
    const int nodebase = g * NPGT, edgebase = g * EPGT;
    const int tid = threadIdx.x, w = tid >> 5, lane = tid & 31;
    const int EPW = EPGT / W;

    for (int i = tid; i < W * NPGT; i += W * 32) ((int*)hw)[i] = 0;
    __syncthreads();

    const int ebase = edgebase + w * EPW;
    for (int c0 = 0; c0 < EPW; c0 += 32) {
        int d = dst[ebase + c0 + lane] - nodebase;
        unsigned mm = __match_any_sync(0xffffffffu, d);
        int leader = __ffs(mm) - 1;
        if (lane == leader) atomicAdd(&hw[w][d], __popc(mm));
    }
    __syncthreads();

    if (tid < NPGT) {
        int deg = 0;
        #pragma unroll
        for (int ww = 0; ww < W; ww++) deg += hw[ww][tid];
        cnt[nodebase + tid] = deg;
        soff[tid] = deg;
    }
    __syncthreads();
    if (tid == 0) {
        int run = 0;
        for (int i = 0; i < NPGT; i++) { int d0 = soff[i]; soff[i] = run; run += d0; }
    }
    __syncthreads();
    if (tid < NPGT) {
        int run = edgebase + soff[tid];
        start[nodebase + tid] = run;
        #pragma unroll
        for (int ww = 0; ww < W; ww++) { int t0 = hw[ww][tid]; hw[ww][tid] = run; run += t0; }
    }
    __syncthreads();

    for (int c0 = 0; c0 < EPW; c0 += 32) {
        int e = ebase + c0 + lane;
        int d = dst[e] - nodebase;
        unsigned mm = __match_any_sync(0xffffffffu, d);
        int leader = __ffs(mm) - 1;
        int r = __popc(mm & ((1u << lane) - 1));
        int basepos = 0;
        if (lane == leader) { basepos = hw[w][d]; hw[w][d] += __popc(mm); }
        basepos = __shfl_sync(0xffffffffu, basepos, leader);
        csr[basepos + r] = e;
    }
}

// ---------------- fp32 -> (hi, lo) bf16 split ----------------
__global__ void split_f32(const float* __restrict__ x, bf16* __restrict__ hi,
                          bf16* __restrict__ lo, int n4)
{
    int i = blockIdx.x * blockDim.x + threadIdx.x;
    if (i >= n4) return;
    float4 v = ((const float4*)x)[i];
    bf162 h0 = __floats2bfloat162_rn(v.x, v.y);
    bf162 h1 = __floats2bfloat162_rn(v.z, v.w);
    bf162 l0 = __floats2bfloat162_rn(v.x - __bfloat162float(h0.x), v.y - __bfloat162float(h0.y));
    bf162 l1 = __floats2bfloat162_rn(v.z - __bfloat162float(h1.x), v.w - __bfloat162float(h1.y));
    ((bf162*)hi)[2 * i] = h0; ((bf162*)hi)[2 * i + 1] = h1;
    ((bf162*)lo)[2 * i] = l0; ((bf162*)lo)[2 * i + 1] = l1;
}

// ---------------- MMA helpers ----------------
__device__ __forceinline__ uint32_t sptr(const void* p) {
    return (uint32_t)__cvta_generic_to_shared(p);
}
__device__ __forceinline__ void ldsm4(uint32_t& r0, uint32_t& r1, uint32_t& r2, uint32_t& r3, uint32_t a) {
    asm volatile("ldmatrix.sync.aligned.m8n8.x4.shared.b16 {%0,%1,%2,%3},[%4];\n"
                 : "=r"(r0), "=r"(r1), "=r"(r2), "=r"(r3) : "r"(a));
}
__device__ __forceinline__ void ldsm4t(uint32_t& r0, uint32_t& r1, uint32_t& r2, uint32_t& r3, uint32_t a) {
    asm volatile("ldmatrix.sync.aligned.m8n8.x4.trans.shared.b16 {%0,%1,%2,%3},[%4];\n"
                 : "=r"(r0), "=r"(r1), "=r"(r2), "=r"(r3) : "r"(a));
}
__device__ __forceinline__ void mma16816(float* c, const uint32_t* a, uint32_t b0, uint32_t b1) {
    asm volatile("mma.sync.aligned.m16n8k16.row.col.f32.bf16.bf16.f32 "
                 "{%0,%1,%2,%3},{%4,%5,%6,%7},{%8,%9},{%0,%1,%2,%3};\n"
                 : "+f"(c[0]), "+f"(c[1]), "+f"(c[2]), "+f"(c[3])
                 : "r"(a[0]), "r"(a[1]), "r"(a[2]), "r"(a[3]), "r"(b0), "r"(b1));
}
__device__ __forceinline__ void cpa16(void* s, const void* g) {
    asm volatile("cp.async.cg.shared.global [%0], [%1], 16;\n" :: "r"(sptr(s)), "l"(g));
}
__device__ __forceinline__ void cpcommit() { asm volatile("cp.async.commit_group;\n"); }
template<int N> __device__ __forceinline__ void cpwait() {
    asm volatile("cp.async.wait_group %0;\n" :: "n"(N));
}

// ---------------- pipelined split-bf16 tensor-core GEMM ----------------
// C[M,128] = (Ah+Al)[M,K] @ (Bh+Bl)[K,128] + bias [+ vg mask] [+ relu]
// outputs either fp32 (Cf) or split bf16 (Ch, Cl).
template<int K>
__global__ __launch_bounds__(256) void gemm_bf16(
    const bf16* __restrict__ Ah, const bf16* __restrict__ Al,
    const bf16* __restrict__ Bh, const bf16* __restrict__ Bl,
    const float* __restrict__ bias,
    float* __restrict__ Cf, bf16* __restrict__ Ch, bf16* __restrict__ Cl,
    const float* __restrict__ vg, const int* __restrict__ cnt, int do_relu)
{
    constexpr int KT = K / 32;
    constexpr int ABUF = 128 * 40;      // elems per A buffer
    extern __shared__ __align__(16) char smem_raw[];
    bf16* sAh = (bf16*)smem_raw;              // [2][128*40]
    bf16* sAl = sAh + 2 * ABUF;
    bf16* sBh = sAl + 2 * ABUF;               // [K*136]
    bf16* sBl = sBh + K * 136;

    int tid = threadIdx.x;
    int wid = tid >> 5, lane = tid & 31;
    int warp_m = wid >> 1, warp_n = wid & 1;
    int row0 = blockIdx.x * 128;

    // B: full [K x 128] tiles
    for (int i = tid; i < K * 16; i += 256) {
        int kk = i >> 4, f = (i & 15) * 8;
        cpa16(sBh + kk * 136 + f, Bh + kk * 128 + f);
        cpa16(sBl + kk * 136 + f, Bl + kk * 128 + f);
    }
    // A tile loader
    auto load_a = [&](int kt, int buf) {
        #pragma unroll
        for (int it = 0; it < 2; it++) {
            int idx = tid + it * 256;
            int m = idx >> 2, f = (idx & 3) * 8;
            cpa16(sAh + buf * ABUF + m * 40 + f, Ah + (size_t)(row0 + m) * K + kt * 32 + f);
            cpa16(sAl + buf * ABUF + m * 40 + f, Al + (size_t)(row0 + m) * K + kt * 32 + f);
        }
    };
    load_a(0, 0); cpcommit();
    if (KT > 1) { load_a(1, 1); cpcommit(); }
    if (KT > 1) cpwait<1>(); else cpwait<0>();
    __syncthreads();

    float acc[2][8][4];
    #pragma unroll
    for (int i = 0; i < 2; i++)
        #pragma unroll
        for (int j = 0; j < 8; j++)
            #pragma unroll
            for (int k = 0; k < 4; k++) acc[i][j][k] = 0.0f;

    for (int kt = 0; kt < KT; kt++) {
        int buf = kt & 1;
        #pragma unroll
        for (int ks = 0; ks < 32; ks += 16) {
            uint32_t ah[2][4], al[2][4];
            #pragma unroll
            for (int mt = 0; mt < 2; mt++) {
                int r = warp_m * 32 + mt * 16 + (lane & 15);
                int c = ks + (lane >> 4) * 8;
                ldsm4(ah[mt][0], ah[mt][1], ah[mt][2], ah[mt][3], sptr(sAh + buf * ABUF + r * 40 + c));
                ldsm4(al[mt][0], al[mt][1], al[mt][2], al[mt][3], sptr(sAl + buf * ABUF + r * 40 + c));
            }
            #pragma unroll
            for (int np = 0; np < 4; np++) {
                int kk = kt * 32 + ks + (lane & 7) + ((lane >> 3) & 1) * 8;
                int cc = warp_n * 64 + np * 16 + (lane >> 4) * 8;
                uint32_t bh[4], bl[4];
                ldsm4t(bh[0], bh[1], bh[2], bh[3], sptr(sBh + kk * 136 + cc));
                ldsm4t(bl[0], bl[1], bl[2], bl[3], sptr(sBl + kk * 136 + cc));
                #pragma unroll
                for (int mt = 0; mt < 2; mt++) {
                    #pragma unroll
                    for (int sub = 0; sub < 2; sub++) {
                        float* c0 = acc[mt][np * 2 + sub];
                        mma16816(c0, ah[mt], bh[sub * 2], bh[sub * 2 + 1]);
                        mma16816(c0, ah[mt], bl[sub * 2], bl[sub * 2 + 1]);
                        mma16816(c0, al[mt], bh[sub * 2], bh[sub * 2 + 1]);
                    }
                }
            }
        }
        if (kt + 1 < KT) {
            __syncthreads();
            if (kt + 2 < KT) { load_a(kt + 2, buf); cpcommit(); cpwait<1>(); }
            else cpwait<0>();
            __syncthreads();
        }
    }

    // epilogue
    #pragma unroll
    for (int mt = 0; mt < 2; mt++) {
        int r0 = row0 + warp_m * 32 + mt * 16 + (lane >> 2);
        #pragma unroll
        for (int nt = 0; nt < 8; nt++) {
            int col = warp_n * 64 + nt * 8 + (lane & 3) * 2;
            float b0 = bias[col], b1 = bias[col + 1];
            float v0 = acc[mt][nt][0] + b0;
            float v1 = acc[mt][nt][1] + b1;
            float v2 = acc[mt][nt][2] + b0;
            float v3 = acc[mt][nt][3] + b1;
            if (vg) {
                int ra = r0, rb = r0 + 8;
                float ma = (cnt[ra] > 0) ? 1.0f : 0.0f;
                float mb = (cnt[rb] > 0) ? 1.0f : 0.0f;
                const float* va = vg + (size_t)(ra >> 9) * HD;
                const float* vb = vg + (size_t)(rb >> 9) * HD;
                v0 += ma * va[col]; v1 += ma * va[col + 1];
                v2 += mb * vb[col]; v3 += mb * vb[col + 1];
            }
            if (do_relu) {
                v0 = fmaxf(v0, 0.f); v1 = fmaxf(v1, 0.f);
                v2 = fmaxf(v2, 0.f); v3 = fmaxf(v3, 0.f);
            }
            if (Cf) {
                *(float2*)(Cf + (size_t)r0 * 128 + col)       = make_float2(v0, v1);
                *(float2*)(Cf + (size_t)(r0 + 8) * 128 + col) = make_float2(v2, v3);
            } else {
                bf162 h01 = __floats2bfloat162_rn(v0, v1);
                bf162 l01 = __floats2bfloat162_rn(v0 - __bfloat162float(h01.x),
                                                  v1 - __bfloat162float(h01.y));
                bf162 h23 = __floats2bfloat162_rn(v2, v3);
                bf162 l23 = __floats2bfloat162_rn(v2 - __bfloat162float(h23.x),
                                                  v3 - __bfloat162float(h23.y));
                *(bf162*)(Ch + (size_t)r0 * 128 + col)       = h01;
                *(bf162*)(Cl + (size_t)r0 * 128 + col)       = l01;
                *(bf162*)(Ch + (size_t)(r0 + 8) * 128 + col) = h23;
                *(bf162*)(Cl + (size_t)(r0 + 8) * 128 + col) = l23;
            }
        }
    }
}

// ---------------- row sum-of-squares (D=128) ----------------
__global__ void row_ssq(const float* __restrict__ h, float* __restrict__ ssq, int N)
{
    int w = (blockIdx.x * blockDim.x + threadIdx.x) >> 5;
    int lane = threadIdx.x & 31;
    if (w >= N) return;
    float4 a = ((const float4*)(h + (size_t)w * HD))[lane];
    float ss = a.x * a.x + a.y * a.y + a.z * a.z + a.w * a.w;
    #pragma unroll
    for (int o = 16; o; o >>= 1) ss += __shfl_xor_sync(0xFFFFFFFFu, ss, o);
    if (lane == 0) ssq[w] = ss;
}

// ---------------- fused AGNN: logits + online softmax + aggregate ----------------
// warp per dst node; optional per-graph extra scalar (folded concat); output fp32 or split bf16
template<bool SPLIT>
__global__ void agnn_fused(const float* __restrict__ h, const float* __restrict__ ssq,
                           const int* __restrict__ csr, const int* __restrict__ start,
                           const int* __restrict__ cnt, const int* __restrict__ src,
                           const float* __restrict__ betas, int l,
                           const float* __restrict__ extra, int shift,
                           float* __restrict__ outf, bf16* __restrict__ outh,
                           bf16* __restrict__ outl, int N)
{
    int n = (blockIdx.x * blockDim.x + threadIdx.x) >> 5;
    int lane = threadIdx.x & 31;
    if (n >= N) return;
    int s0 = start[n];
    int c  = cnt[n];
    float4 acc = make_float4(0.f, 0.f, 0.f, 0.f);
    if (c > 0) {
        float beta = betas[l];
        float ex = extra ? extra[n >> shift] : 0.0f;
        float invd = rsqrtf(ssq[n] + ex + 1e-24f);
        float4 hd = ((const float4*)(h + (size_t)n * HD))[lane];
        float m = -CUDART_INF_F, den = 0.0f;
        for (int j = 0; j < c; j++) {
            int eid = csr[s0 + j];
            int s = src[eid];
            float4 a = ((const float4*)(h + (size_t)s * HD))[lane];
            float dot = a.x * hd.x + a.y * hd.y + a.z * hd.z + a.w * hd.w;
            #pragma unroll
            for (int o = 16; o; o >>= 1) dot += __shfl_xor_sync(0xFFFFFFFFu, dot, o);
            float e = beta * (dot + ex) * rsqrtf(ssq[s] + ex + 1e-24f) * invd;
            float nm = fmaxf(m, e);
            float corr = __expf(m - nm);
            float p = __expf(e - nm);
            den = den * corr + p;
            acc.x = acc.x * corr + p * a.x;
            acc.y = acc.y * corr + p * a.y;
            acc.z = acc.z * corr + p * a.z;
            acc.w = acc.w * corr + p * a.w;
            m = nm;
        }
        float r = 1.0f / fmaxf(den, 1e-24f);
        acc.x *= r; acc.y *= r; acc.z *= r; acc.w *= r;
    }
    if (SPLIT) {
        bf162 h0 = __floats2bfloat162_rn(acc.x, acc.y);
        bf162 h1 = __floats2bfloat162_rn(acc.z, acc.w);
        bf162 l0 = __floats2bfloat162_rn(acc.x - __bfloat162float(h0.x),
                                         acc.y - __bfloat162float(h0.y));
        bf162 l1 = __floats2bfloat162_rn(acc.z - __bfloat162float(h1.x),
                                         acc.w - __bfloat162float(h1.y));
        bf162* oh = (bf162*)(outh + (size_t)n * HD);
        bf162* ol = (bf162*)(outl + (size_t)n * HD);
        oh[2 * lane] = h0; oh[2 * lane + 1] = h1;
        ol[2 * lane] = l0; ol[2 * lane + 1] = l1;
    } else {
        ((float4*)(outf + (size_t)n * HD))[lane] = acc;
    }
}

// ---------------- per-graph sum pool (4-way parallel) ----------------
__global__ void pool_sum2(const float* __restrict__ h, float* __restrict__ out, int per_graph)
{
    __shared__ float s[512];
    int g = blockIdx.x, t = threadIdx.x;
    int col = t & 127, part = t >> 7;
    float acc = 0.0f;
    for (int j = part; j < per_graph; j += 4)
        acc += h[((size_t)g * per_graph + j) * HD + col];
    s[t] = acc;
    __syncthreads();
    if (part == 0) out[g * HD + col] = s[col] + s[col + 128] + s[col + 256] + s[col + 384];
}

// ---------------- per-graph ssq of aggr ----------------
__global__ void graph_ssq(const float* __restrict__ aggr, float* __restrict__ ssqa)
{
    __shared__ float s[128];
    int g = blockIdx.x, t = threadIdx.x;
    float v = aggr[g * HD + t];
    s[t] = v * v;
    __syncthreads();
    #pragma unroll
    for (int o = 64; o; o >>= 1) {
        if (t < o) s[t] += s[t + o];
        __syncthreads();
    }
    if (t == 0) ssqa[g] = s[0];
}

// ---------------- per-graph v_g = aggr_g @ W1_bot ----------------
__global__ void vg_gemm(const float* __restrict__ aggr, const float* __restrict__ W1bot,
                        float* __restrict__ vg)
{
    __shared__ float s[128];
    int g = blockIdx.x, t = threadIdx.x;
    s[t] = aggr[g * HD + t];
    __syncthreads();
    float a = 0.0f;
    #pragma unroll 8
    for (int k = 0; k < HD; k++) a += s[k] * W1bot[k * HD + t];
    vg[g * HD + t] = a;
}

// ---------------- final predictor ----------------
__global__ void predictor(const float* __restrict__ hgsum, const float* __restrict__ Wp1,
                          const float* __restrict__ bp1, const float* __restrict__ Wp2,
                          const float* __restrict__ bp2, float* __restrict__ y)
{
    __shared__ float srow[HD];
    __shared__ float st[HD];
    int g = blockIdx.x, t = threadIdx.x;
    srow[t] = hgsum[g * HD + t];
    __syncthreads();
    float a = 0.0f;
    #pragma unroll 8
    for (int k = 0; k < HD; k++) a += srow[k] * Wp1[k * HD + t];
    st[t] = fmaxf(a + bp1[t], 0.0f) * Wp2[t];
    __syncthreads();
    #pragma unroll
    for (int s = 64; s; s >>= 1) {
        if (t < s) st[t] += st[t + s];
        __syncthreads();
    }
    if (t == 0) y[g] = st[0] + bp2[0];
}

// ---------------- launch ----------------
extern "C" void kernel_launch(void* const* d_in, const int* in_sizes, int n_in,
                              void* d_out, int out_size)
{
    const float* X     = (const float*)d_in[0];
    const float* Xq    = (const float*)d_in[1];
    const int*   g_src = (const int*)d_in[2];
    const int*   g_dst = (const int*)d_in[3];
    const int*   q_src = (const int*)d_in[5];
    const int*   q_dst = (const int*)d_in[6];
    const float* Wg    = (const float*)d_in[8];
    const float* bg    = (const float*)d_in[9];
    const float* Wq    = (const float*)d_in[10];
    const float* bq    = (const float*)d_in[11];
    const float* betas_g = (const float*)d_in[12];
    const float* betas_q = (const float*)d_in[13];
    const float* W1r   = (const float*)d_in[14];
    const float* b1r   = (const float*)d_in[15];
    const float* W2r   = (const float*)d_in[16];
    const float* b2r   = (const float*)d_in[17];
    const float* Wp1   = (const float*)d_in[18];
    const float* bp1   = (const float*)d_in[19];
    const float* Wp2   = (const float*)d_in[20];
    const float* bp2   = (const float*)d_in[21];
    float* y = (float*)d_out;

    float *hg, *hqA, *hqB, *ssqq, *ssqg, *ssqa, *hqaggr, *vg, *hgsum;
    bf16 *Xh, *Xl, *Xqh, *Xql, *Wh, *Wl, *aggh, *aggl, *t1h, *t1l;
    int *csrg, *startg, *cntg, *csrq, *startq, *cntq;
    cudaGetSymbolAddress((void**)&hg, d_hg);
    cudaGetSymbolAddress((void**)&hqA, d_hqA);
    cudaGetSymbolAddress((void**)&hqB, d_hqB);
    cudaGetSymbolAddress((void**)&ssqq, d_ssqq);
    cudaGetSymbolAddress((void**)&ssqg, d_ssqg);
    cudaGetSymbolAddress((void**)&ssqa, d_ssqa);
    cudaGetSymbolAddress((void**)&hqaggr, d_hqaggr);
    cudaGetSymbolAddress((void**)&vg, d_vg);
    cudaGetSymbolAddress((void**)&hgsum, d_hgsum);
    cudaGetSymbolAddress((void**)&Xh, d_Xh);
    cudaGetSymbolAddress((void**)&Xl, d_Xl);
    cudaGetSymbolAddress((void**)&Xqh, d_Xqh);
    cudaGetSymbolAddress((void**)&Xql, d_Xql);
    cudaGetSymbolAddress((void**)&Wh, d_Wh);
    cudaGetSymbolAddress((void**)&Wl, d_Wl);
    cudaGetSymbolAddress((void**)&aggh, d_aggh);
    cudaGetSymbolAddress((void**)&aggl, d_aggl);
    cudaGetSymbolAddress((void**)&t1h, d_t1h);
    cudaGetSymbolAddress((void**)&t1l, d_t1l);
    cudaGetSymbolAddress((void**)&csrg, d_csrg);
    cudaGetSymbolAddress((void**)&startg, d_startg);
    cudaGetSymbolAddress((void**)&cntg, d_cntg);
    cudaGetSymbolAddress((void**)&csrq, d_csrq);
    cudaGetSymbolAddress((void**)&startq, d_startq);
    cudaGetSymbolAddress((void**)&cntq, d_cntq);

    const int SMEM64  = 2 * (2 * 128 * 40 * 2) + 64 * 136 * 2 * 2;    // 75776
    const int SMEM128 = 2 * (2 * 128 * 40 * 2) + 128 * 136 * 2 * 2;   // 110592
    cudaFuncSetAttribute(gemm_bf16<64>,  cudaFuncAttributeMaxDynamicSharedMemorySize, SMEM64);
    cudaFuncSetAttribute(gemm_bf16<128>, cudaFuncAttributeMaxDynamicSharedMemorySize, SMEM128);

    // CSR build
    build_csr2<NPG, EGE / NB, 16><<<NB, 512>>>(g_dst, csrg, startg, cntg);
    build_csr2<NQPG, EQE / NB, 4><<<NB, 128>>>(q_dst, csrq, startq, cntq);

    // splits: inputs + weights
    split_f32<<<NGN * FIN / 4 / 256, 256>>>(X, Xh, Xl, NGN * FIN / 4);
    split_f32<<<NQN * FIN / 4 / 256, 256>>>(Xq, Xqh, Xql, NQN * FIN / 4);
    split_f32<<<FIN * HD / 4 / 64, 64>>>(Wg, Wh + 0 * HD * HD, Wl + 0 * HD * HD, FIN * HD / 4);
    split_f32<<<FIN * HD / 4 / 64, 64>>>(Wq, Wh + 1 * HD * HD, Wl + 1 * HD * HD, FIN * HD / 4);
    for (int l = 0; l < NL; l++) {
        split_f32<<<HD * HD / 4 / 64, 64>>>(W1r + (size_t)l * 2 * HD * HD,
                                            Wh + (2 + 2 * l) * HD * HD, Wl + (2 + 2 * l) * HD * HD, HD * HD / 4);
        split_f32<<<HD * HD / 4 / 64, 64>>>(W2r + (size_t)l * HD * HD,
                                            Wh + (3 + 2 * l) * HD * HD, Wl + (3 + 2 * l) * HD * HD, HD * HD / 4);
    }

    // input projections
    gemm_bf16<64><<<NGN / 128, 256, SMEM64>>>(Xh, Xl, Wh, Wl, bg, hg,
                                              nullptr, nullptr, nullptr, nullptr, 0);
    gemm_bf16<64><<<NQN / 128, 256, SMEM64>>>(Xqh, Xql, Wh + HD * HD, Wl + HD * HD, bq, hqA,
                                              nullptr, nullptr, nullptr, nullptr, 0);

    float* hq_cur = hqA;
    float* hq_nxt = hqB;
    for (int l = 0; l < NL; l++) {
        // query AGNN (fused)
        row_ssq<<<NQN / 8, 256>>>(hq_cur, ssqq, NQN);
        agnn_fused<false><<<NQN / 8, 256>>>(hq_cur, ssqq, csrq, startq, cntq, q_src,
                                            betas_q, l, nullptr, 0, hq_nxt, nullptr, nullptr, NQN);
        pool_sum2<<<NB, 512>>>(hq_nxt, hqaggr, NQPG);
        graph_ssq<<<NB, 128>>>(hqaggr, ssqa);
        vg_gemm<<<NB, 128>>>(hqaggr, W1r + (size_t)l * 2 * HD * HD + HD * HD, vg);
        // data-graph AGNN (fused, concat folded, split bf16 output)
        row_ssq<<<NGN / 8, 256>>>(hg, ssqg, NGN);
        agnn_fused<true><<<NGN / 8, 256>>>(hg, ssqg, csrg, startg, cntg, g_src,
                                           betas_g, l, ssqa, 9, nullptr, aggh, aggl, NGN);
        // MLP reduce
        gemm_bf16<128><<<NGN / 128, 256, SMEM128>>>(aggh, aggl,
            Wh + (2 + 2 * l) * HD * HD, Wl + (2 + 2 * l) * HD * HD,
            b1r + l * HD, nullptr, t1h, t1l, vg, cntg, 1);
        gemm_bf16<128><<<NGN / 128, 256, SMEM128>>>(t1h, t1l,
            Wh + (3 + 2 * l) * HD * HD, Wl + (3 + 2 * l) * HD * HD,
            b2r + l * HD, hg, nullptr, nullptr, nullptr, nullptr, 0);
        float* tmp = hq_cur; hq_cur = hq_nxt; hq_nxt = tmp;
    }

    pool_sum2<<<NB, 512>>>(hg, hgsum, NPG);
    predictor<<<NB, 128>>>(hgsum, Wp1, bp1, Wp2, bp2, y);
}

// round 4
// speedup vs baseline: 3.5800x; 1.6978x over previous
#include <cuda_runtime.h>
#include <cuda_bf16.h>
#include <math_constants.h>
#include <cstdint>

#define NB    256
#define NPG   512
#define NGN   131072
#define EGE   1048576
#define NQPG  16
#define NQN   4096
#define EQE   32768
#define FIN   64
#define HD    128
#define NL    2

typedef __nv_bfloat16 bf16;
typedef __nv_bfloat162 bf162;

// ---------------- device scratch ----------------
__device__ __align__(16) float d_hg[NGN * HD];
__device__ __align__(16) float d_hqA[NQN * HD];
__device__ __align__(16) float d_hqB[NQN * HD];
__device__ __align__(16) float d_agg[NGN * HD];
__device__ float d_ssqg[NGN];
__device__ float d_ssqqA[NQN];
__device__ float d_ssqqB[NQN];
__device__ float d_ssqa[NB];
__device__ float d_vg[NB * HD];
__device__ int d_csrg[EGE];
__device__ int d_startg[NGN];
__device__ int d_cntg[NGN];
__device__ int d_csrq[EQE];
__device__ int d_startq[NQN];
__device__ int d_cntq[NQN];

// ---------------- O(E) deterministic CSR build ----------------
template<int NPGT, int EPGT, int W>
__global__ void build_csr2(const int* __restrict__ dst,
                           int* __restrict__ csr,
                           int* __restrict__ start,
                           int* __restrict__ cnt)
{
    __shared__ int hw[W][NPGT];
    __shared__ int soff[NPGT];
    const int g = blockIdx.x;
    const int nodebase = g * NPGT, edgebase = g * EPGT;
    const int tid = threadIdx.x, w = tid >> 5, lane = tid & 31;
    const int EPW = EPGT / W;

    for (int i = tid; i < W * NPGT; i += W * 32) ((int*)hw)[i] = 0;
    __syncthreads();

    const int ebase = edgebase + w * EPW;
    for (int c0 = 0; c0 < EPW; c0 += 32) {
        int d = dst[ebase + c0 + lane] - nodebase;
        unsigned mm = __match_any_sync(0xffffffffu, d);
        int leader = __ffs(mm) - 1;
        if (lane == leader) atomicAdd(&hw[w][d], __popc(mm));
    }
    __syncthreads();

    if (tid < NPGT) {
        int deg = 0;
        #pragma unroll
        for (int ww = 0; ww < W; ww++) deg += hw[ww][tid];
        cnt[nodebase + tid] = deg;
        soff[tid] = deg;
    }
    __syncthreads();
    if (tid == 0) {
        int run = 0;
        for (int i = 0; i < NPGT; i++) { int d0 = soff[i]; soff[i] = run; run += d0; }
    }
    __syncthreads();
    if (tid < NPGT) {
        int run = edgebase + soff[tid];
        start[nodebase + tid] = run;
        #pragma unroll
        for (int ww = 0; ww < W; ww++) { int t0 = hw[ww][tid]; hw[ww][tid] = run; run += t0; }
    }
    __syncthreads();

    for (int c0 = 0; c0 < EPW; c0 += 32) {
        int e = ebase + c0 + lane;
        int d = dst[e] - nodebase;
        unsigned mm = __match_any_sync(0xffffffffu, d);
        int leader = __ffs(mm) - 1;
        int r = __popc(mm & ((1u << lane) - 1));
        int basepos = 0;
        if (lane == leader) { basepos = hw[w][d]; hw[w][d] += __popc(mm); }
        basepos = __shfl_sync(0xffffffffu, basepos, leader);
        csr[basepos + r] = e;
    }
}

// ---------------- MMA helpers ----------------
__device__ __forceinline__ uint32_t sptr(const void* p) {
    return (uint32_t)__cvta_generic_to_shared(p);
}
__device__ __forceinline__ void ldsm4(uint32_t& r0, uint32_t& r1, uint32_t& r2, uint32_t& r3, uint32_t a) {
    asm volatile("ldmatrix.sync.aligned.m8n8.x4.shared.b16 {%0,%1,%2,%3},[%4];\n"
                 : "=r"(r0), "=r"(r1), "=r"(r2), "=r"(r3) : "r"(a));
}
__device__ __forceinline__ void ldsm4t(uint32_t& r0, uint32_t& r1, uint32_t& r2, uint32_t& r3, uint32_t a) {
    asm volatile("ldmatrix.sync.aligned.m8n8.x4.trans.shared.b16 {%0,%1,%2,%3},[%4];\n"
                 : "=r"(r0), "=r"(r1), "=r"(r2), "=r"(r3) : "r"(a));
}
__device__ __forceinline__ void mma16816(float* c, const uint32_t* a, uint32_t b0, uint32_t b1) {
    asm volatile("mma.sync.aligned.m16n8k16.row.col.f32.bf16.bf16.f32 "
                 "{%0,%1,%2,%3},{%4,%5,%6,%7},{%8,%9},{%0,%1,%2,%3};\n"
                 : "+f"(c[0]), "+f"(c[1]), "+f"(c[2]), "+f"(c[3])
                 : "r"(a[0]), "r"(a[1]), "r"(a[2]), "r"(a[3]), "r"(b0), "r"(b1));
}
__device__ __forceinline__ void split_store(bf16* hi, bf16* lo, float x, float y) {
    bf162 h = __floats2bfloat162_rn(x, y);
    bf162 l = __floats2bfloat162_rn(x - __bfloat162float(h.x), y - __bfloat162float(h.y));
    *(bf162*)hi = h;
    *(bf162*)lo = l;
}

// deterministic per-row ssq reduction helper (quad shuffle)
__device__ __forceinline__ float quadsum(float v) {
    v += __shfl_xor_sync(0xffffffffu, v, 1);
    v += __shfl_xor_sync(0xffffffffu, v, 2);
    return v;
}

// ---------------- input projection GEMM (K=64, fp32 in, split in-kernel, ssq epilogue) ----------------
__global__ __launch_bounds__(256) void gemm_in(
    const float* __restrict__ A, const float* __restrict__ W,
    const float* __restrict__ bias, float* __restrict__ C, float* __restrict__ ssq_out)
{
    extern __shared__ __align__(16) char sm[];
    bf16* sAh = (bf16*)sm;                     // 128*72
    bf16* sAl = sAh + 128 * 72;
    bf16* sBh = sAl + 128 * 72;                // 64*136
    bf16* sBl = sBh + 64 * 136;
    float* sred = (float*)(sBl + 64 * 136);    // [2][128]

    int tid = threadIdx.x;
    int wid = tid >> 5, lane = tid & 31;
    int warp_m = wid >> 1, warp_n = wid & 1;
    int row0 = blockIdx.x * 128;

    sred[tid] = 0.0f;  // 256 = 2*128

    // A [128 x 64] fp32 -> split
    #pragma unroll
    for (int it = 0; it < 8; it++) {
        int idx = tid + it * 256;
        int m = idx >> 4, f = (idx & 15) * 4;
        float4 v = *(const float4*)(A + (size_t)(row0 + m) * FIN + f);
        split_store(&sAh[m * 72 + f],     &sAl[m * 72 + f],     v.x, v.y);
        split_store(&sAh[m * 72 + f + 2], &sAl[m * 72 + f + 2], v.z, v.w);
    }
    // W [64 x 128] fp32 -> split
    #pragma unroll
    for (int it = 0; it < 8; it++) {
        int idx = tid + it * 256;
        int kk = idx >> 5, f = (idx & 31) * 4;
        float4 v = *(const float4*)(W + (size_t)kk * 128 + f);
        split_store(&sBh[kk * 136 + f],     &sBl[kk * 136 + f],     v.x, v.y);
        split_store(&sBh[kk * 136 + f + 2], &sBl[kk * 136 + f + 2], v.z, v.w);
    }
    __syncthreads();

    float acc[2][8][4];
    #pragma unroll
    for (int i = 0; i < 2; i++)
        #pragma unroll
        for (int j = 0; j < 8; j++)
            #pragma unroll
            for (int k = 0; k < 4; k++) acc[i][j][k] = 0.0f;

    #pragma unroll
    for (int ks = 0; ks < FIN; ks += 16) {
        uint32_t ah[2][4], al[2][4];
        #pragma unroll
        for (int mt = 0; mt < 2; mt++) {
            int r = warp_m * 32 + mt * 16 + (lane & 15);
            int c = ks + (lane >> 4) * 8;
            ldsm4(ah[mt][0], ah[mt][1], ah[mt][2], ah[mt][3], sptr(sAh + r * 72 + c));
            ldsm4(al[mt][0], al[mt][1], al[mt][2], al[mt][3], sptr(sAl + r * 72 + c));
        }
        #pragma unroll
        for (int np = 0; np < 4; np++) {
            int kk = ks + (lane & 7) + ((lane >> 3) & 1) * 8;
            int cc = warp_n * 64 + np * 16 + (lane >> 4) * 8;
            uint32_t bh[4], bl[4];
            ldsm4t(bh[0], bh[1], bh[2], bh[3], sptr(sBh + kk * 136 + cc));
            ldsm4t(bl[0], bl[1], bl[2], bl[3], sptr(sBl + kk * 136 + cc));
            #pragma unroll
            for (int mt = 0; mt < 2; mt++) {
                #pragma unroll
                for (int sub = 0; sub < 2; sub++) {
                    float* c0 = acc[mt][np * 2 + sub];
                    mma16816(c0, ah[mt], bh[sub * 2], bh[sub * 2 + 1]);
                    mma16816(c0, ah[mt], bl[sub * 2], bl[sub * 2 + 1]);
                    mma16816(c0, al[mt], bh[sub * 2], bh[sub * 2 + 1]);
                }
            }
        }
    }

    // epilogue: bias, write C fp32, row ssq (deterministic)
    #pragma unroll
    for (int mt = 0; mt < 2; mt++) {
        int rA = warp_m * 32 + mt * 16 + (lane >> 2);
        int rB = rA + 8;
        float ssA = 0.f, ssB = 0.f;
        #pragma unroll
        for (int nt = 0; nt < 8; nt++) {
            int col = warp_n * 64 + nt * 8 + (lane & 3) * 2;
            float b0 = bias[col], b1 = bias[col + 1];
            float v0 = acc[mt][nt][0] + b0;
            float v1 = acc[mt][nt][1] + b1;
            float v2 = acc[mt][nt][2] + b0;
            float v3 = acc[mt][nt][3] + b1;
            *(float2*)(C + (size_t)(row0 + rA) * 128 + col) = make_float2(v0, v1);
            *(float2*)(C + (size_t)(row0 + rB) * 128 + col) = make_float2(v2, v3);
            ssA += v0 * v0 + v1 * v1;
            ssB += v2 * v2 + v3 * v3;
        }
        ssA = quadsum(ssA); ssB = quadsum(ssB);
        if ((lane & 3) == 0) {
            sred[warp_n * 128 + rA] = ssA;
            sred[warp_n * 128 + rB] = ssB;
        }
    }
    __syncthreads();
    if (tid < 128 && ssq_out) ssq_out[row0 + tid] = sred[tid] + sred[128 + tid];
}

// ---------------- fused MLP: hg = relu(agg@W1 + vg*mask + b1) @ W2 + b2, + ssq ----------------
__global__ __launch_bounds__(256) void mlp_fused(
    const float* __restrict__ A, const float* __restrict__ W1, const float* __restrict__ W2,
    const float* __restrict__ bias1, const float* __restrict__ bias2,
    const float* __restrict__ vg, const int* __restrict__ cnt,
    float* __restrict__ Cout, float* __restrict__ ssq_out)
{
    extern __shared__ __align__(16) char sm[];
    bf16* sAh = (bf16*)sm;                       // 128*136
    bf16* sAl = sAh + 128 * 136;
    bf16* sBh = sAl + 128 * 136;                 // 128*136
    bf16* sBl = sBh + 128 * 136;
    float* sred = (float*)(sBl + 128 * 136);

    int tid = threadIdx.x;
    int wid = tid >> 5, lane = tid & 31;
    int warp_m = wid >> 1, warp_n = wid & 1;
    int row0 = blockIdx.x * 128;

    sred[tid] = 0.0f;

    // A [128 x 128] fp32 -> split ; W1 [128 x 128] fp32 -> split
    #pragma unroll
    for (int it = 0; it < 16; it++) {
        int idx = tid + it * 256;
        int r = idx >> 5, f = (idx & 31) * 4;
        float4 v = *(const float4*)(A + (size_t)(row0 + r) * 128 + f);
        split_store(&sAh[r * 136 + f],     &sAl[r * 136 + f],     v.x, v.y);
        split_store(&sAh[r * 136 + f + 2], &sAl[r * 136 + f + 2], v.z, v.w);
        float4 w = *(const float4*)(W1 + (size_t)r * 128 + f);
        split_store(&sBh[r * 136 + f],     &sBl[r * 136 + f],     w.x, w.y);
        split_store(&sBh[r * 136 + f + 2], &sBl[r * 136 + f + 2], w.z, w.w);
    }
    __syncthreads();

    float acc[2][8][4];
    #pragma unroll
    for (int i = 0; i < 2; i++)
        #pragma unroll
        for (int j = 0; j < 8; j++)
            #pragma unroll
            for (int k = 0; k < 4; k++) acc[i][j][k] = 0.0f;

    // -------- stage 1 GEMM --------
    #pragma unroll
    for (int ks = 0; ks < 128; ks += 16) {
        uint32_t ah[2][4], al[2][4];
        #pragma unroll
        for (int mt = 0; mt < 2; mt++) {
            int r = warp_m * 32 + mt * 16 + (lane & 15);
            int c = ks + (lane >> 4) * 8;
            ldsm4(ah[mt][0], ah[mt][1], ah[mt][2], ah[mt][3], sptr(sAh + r * 136 + c));
            ldsm4(al[mt][0], al[mt][1], al[mt][2], al[mt][3], sptr(sAl + r * 136 + c));
        }
        #pragma unroll
        for (int np = 0; np < 4; np++) {
            int kk = ks + (lane & 7) + ((lane >> 3) & 1) * 8;
            int cc = warp_n * 64 + np * 16 + (lane >> 4) * 8;
            uint32_t bh[4], bl[4];
            ldsm4t(bh[0], bh[1], bh[2], bh[3], sptr(sBh + kk * 136 + cc));
            ldsm4t(bl[0], bl[1], bl[2], bl[3], sptr(sBl + kk * 136 + cc));
            #pragma unroll
            for (int mt = 0; mt < 2; mt++) {
                #pragma unroll
                for (int sub = 0; sub < 2; sub++) {
                    float* c0 = acc[mt][np * 2 + sub];
                    mma16816(c0, ah[mt], bh[sub * 2], bh[sub * 2 + 1]);
                    mma16816(c0, ah[mt], bl[sub * 2], bl[sub * 2 + 1]);
                    mma16816(c0, al[mt], bh[sub * 2], bh[sub * 2 + 1]);
                }
            }
        }
    }
    __syncthreads();   // done reading sA/sB for stage 1

    // stage-1 epilogue: bias1 + vg mask + relu -> t1 split into sA
    #pragma unroll
    for (int mt = 0; mt < 2; mt++) {
        int rA = warp_m * 32 + mt * 16 + (lane >> 2);
        int rB = rA + 8;
        int gA = row0 + rA, gB = row0 + rB;
        float mA = (cnt[gA] > 0) ? 1.0f : 0.0f;
        float mB = (cnt[gB] > 0) ? 1.0f : 0.0f;
        const float* vA = vg + (size_t)(gA >> 9) * HD;
        const float* vB = vg + (size_t)(gB >> 9) * HD;
        #pragma unroll
        for (int nt = 0; nt < 8; nt++) {
            int col = warp_n * 64 + nt * 8 + (lane & 3) * 2;
            float b0 = bias1[col], b1 = bias1[col + 1];
            float v0 = fmaxf(acc[mt][nt][0] + b0 + mA * vA[col],     0.f);
            float v1 = fmaxf(acc[mt][nt][1] + b1 + mA * vA[col + 1], 0.f);
            float v2 = fmaxf(acc[mt][nt][2] + b0 + mB * vB[col],     0.f);
            float v3 = fmaxf(acc[mt][nt][3] + b1 + mB * vB[col + 1], 0.f);
            split_store(&sAh[rA * 136 + col], &sAl[rA * 136 + col], v0, v1);
            split_store(&sAh[rB * 136 + col], &sAl[rB * 136 + col], v2, v3);
            acc[mt][nt][0] = 0.f; acc[mt][nt][1] = 0.f;
            acc[mt][nt][2] = 0.f; acc[mt][nt][3] = 0.f;
        }
    }
    // load W2 -> sB
    #pragma unroll
    for (int it = 0; it < 16; it++) {
        int idx = tid + it * 256;
        int r = idx >> 5, f = (idx & 31) * 4;
        float4 w = *(const float4*)(W2 + (size_t)r * 128 + f);
        split_store(&sBh[r * 136 + f],     &sBl[r * 136 + f],     w.x, w.y);
        split_store(&sBh[r * 136 + f + 2], &sBl[r * 136 + f + 2], w.z, w.w);
    }
    __syncthreads();

    // -------- stage 2 GEMM --------
    #pragma unroll
    for (int ks = 0; ks < 128; ks += 16) {
        uint32_t ah[2][4], al[2][4];
        #pragma unroll
        for (int mt = 0; mt < 2; mt++) {
            int r = warp_m * 32 + mt * 16 + (lane & 15);
            int c = ks + (lane >> 4) * 8;
            ldsm4(ah[mt][0], ah[mt][1], ah[mt][2], ah[mt][3], sptr(sAh + r * 136 + c));
            ldsm4(al[mt][0], al[mt][1], al[mt][2], al[mt][3], sptr(sAl + r * 136 + c));
        }
        #pragma unroll
        for (int np = 0; np < 4; np++) {
            int kk = ks + (lane & 7) + ((lane >> 3) & 1) * 8;
            int cc = warp_n * 64 + np * 16 + (lane >> 4) * 8;
            uint32_t bh[4], bl[4];
            ldsm4t(bh[0], bh[1], bh[2], bh[3], sptr(sBh + kk * 136 + cc));
            ldsm4t(bl[0], bl[1], bl[2], bl[3], sptr(sBl + kk * 136 + cc));
            #pragma unroll
            for (int mt = 0; mt < 2; mt++) {
                #pragma unroll
                for (int sub = 0; sub < 2; sub++) {
                    float* c0 = acc[mt][np * 2 + sub];
                    mma16816(c0, ah[mt], bh[sub * 2], bh[sub * 2 + 1]);
                    mma16816(c0, ah[mt], bl[sub * 2], bl[sub * 2 + 1]);
                    mma16816(c0, al[mt], bh[sub * 2], bh[sub * 2 + 1]);
                }
            }
        }
    }

    // stage-2 epilogue: bias2, write hg fp32, ssq
    #pragma unroll
    for (int mt = 0; mt < 2; mt++) {
        int rA = warp_m * 32 + mt * 16 + (lane >> 2);
        int rB = rA + 8;
        float ssA = 0.f, ssB = 0.f;
        #pragma unroll
        for (int nt = 0; nt < 8; nt++) {
            int col = warp_n * 64 + nt * 8 + (lane & 3) * 2;
            float b0 = bias2[col], b1 = bias2[col + 1];
            float v0 = acc[mt][nt][0] + b0;
            float v1 = acc[mt][nt][1] + b1;
            float v2 = acc[mt][nt][2] + b0;
            float v3 = acc[mt][nt][3] + b1;
            *(float2*)(Cout + (size_t)(row0 + rA) * 128 + col) = make_float2(v0, v1);
            *(float2*)(Cout + (size_t)(row0 + rB) * 128 + col) = make_float2(v2, v3);
            ssA += v0 * v0 + v1 * v1;
            ssB += v2 * v2 + v3 * v3;
        }
        ssA = quadsum(ssA); ssB = quadsum(ssB);
        if ((lane & 3) == 0) {
            sred[warp_n * 128 + rA] = ssA;
            sred[warp_n * 128 + rB] = ssB;
        }
    }
    __syncthreads();
    if (tid < 128) ssq_out[row0 + tid] = sred[tid] + sred[128 + tid];
}

// ---------------- fused AGNN: logits + online softmax + aggregate (+optional out ssq) ----------------
__global__ void agnn_fused(const float* __restrict__ h, const float* __restrict__ ssq,
                           const int* __restrict__ csr, const int* __restrict__ start,
                           const int* __restrict__ cnt, const int* __restrict__ src,
                           const float* __restrict__ betas, int l,
                           const float* __restrict__ extra, int shift,
                           float* __restrict__ outf, float* __restrict__ ssq_out, int N)
{
    int n = (blockIdx.x * blockDim.x + threadIdx.x) >> 5;
    int lane = threadIdx.x & 31;
    if (n >= N) return;
    int s0 = start[n];
    int c  = cnt[n];
    float4 acc = make_float4(0.f, 0.f, 0.f, 0.f);
    if (c > 0) {
        float beta = betas[l];
        float ex = extra ? extra[n >> shift] : 0.0f;
        float invd = rsqrtf(ssq[n] + ex + 1e-24f);
        float4 hd = ((const float4*)(h + (size_t)n * HD))[lane];
        float m = -CUDART_INF_F, den = 0.0f;
        for (int j = 0; j < c; j++) {
            int eid = csr[s0 + j];
            int s = src[eid];
            float4 a = ((const float4*)(h + (size_t)s * HD))[lane];
            float dot = a.x * hd.x + a.y * hd.y + a.z * hd.z + a.w * hd.w;
            #pragma unroll
            for (int o = 16; o; o >>= 1) dot += __shfl_xor_sync(0xFFFFFFFFu, dot, o);
            float e = beta * (dot + ex) * rsqrtf(ssq[s] + ex + 1e-24f) * invd;
            float nm = fmaxf(m, e);
            float corr = __expf(m - nm);
            float p = __expf(e - nm);
            den = den * corr + p;
            acc.x = acc.x * corr + p * a.x;
            acc.y = acc.y * corr + p * a.y;
            acc.z = acc.z * corr + p * a.z;
            acc.w = acc.w * corr + p * a.w;
            m = nm;
        }
        float r = 1.0f / fmaxf(den, 1e-24f);
        acc.x *= r; acc.y *= r; acc.z *= r; acc.w *= r;
    }
    ((float4*)(outf + (size_t)n * HD))[lane] = acc;
    if (ssq_out) {
        float ss = acc.x * acc.x + acc.y * acc.y + acc.z * acc.z + acc.w * acc.w;
        #pragma unroll
        for (int o = 16; o; o >>= 1) ss += __shfl_xor_sync(0xFFFFFFFFu, ss, o);
        if (lane == 0) ssq_out[n] = ss;
    }
}

// ---------------- fused query pool: hqaggr (internal), ssqa, vg = aggr@W1bot ----------------
__global__ void pool_vg(const float* __restrict__ hq, const float* __restrict__ W1bot,
                        float* __restrict__ ssqa, float* __restrict__ vgout)
{
    __shared__ float srow[HD];
    __shared__ float st[HD];
    int g = blockIdx.x, t = threadIdx.x;   // 128 threads
    float a = 0.0f;
    #pragma unroll
    for (int j = 0; j < NQPG; j++) a += hq[((size_t)g * NQPG + j) * HD + t];
    srow[t] = a;
    st[t] = a * a;
    __syncthreads();
    #pragma unroll
    for (int o = 64; o; o >>= 1) {
        if (t < o) st[t] += st[t + o];
        __syncthreads();
    }
    if (t == 0) ssqa[g] = st[0];
    float v = 0.0f;
    #pragma unroll 8
    for (int k = 0; k < HD; k++) v += srow[k] * W1bot[k * HD + t];
    vgout[g * HD + t] = v;
}

// ---------------- final pool + predictor ----------------
__global__ void pool_pred(const float* __restrict__ hg, const float* __restrict__ Wp1,
                          const float* __restrict__ bp1, const float* __restrict__ Wp2,
                          const float* __restrict__ bp2, float* __restrict__ y)
{
    __shared__ float s[512];
    __shared__ float srow[HD];
    __shared__ float st[HD];
    int g = blockIdx.x, t = threadIdx.x;   // 512 threads
    int col = t & 127, part = t >> 7;
    float acc = 0.0f;
    for (int j = part; j < NPG; j += 4)
        acc += hg[((size_t)g * NPG + j) * HD + col];
    s[t] = acc;
    __syncthreads();
    if (part == 0) srow[col] = s[col] + s[col + 128] + s[col + 256] + s[col + 384];
    __syncthreads();
    if (t < 128) {
        float a = 0.0f;
        #pragma unroll 8
        for (int k = 0; k < HD; k++) a += srow[k] * Wp1[k * HD + t];
        st[t] = fmaxf(a + bp1[t], 0.0f) * Wp2[t];
    }
    __syncthreads();
    #pragma unroll
    for (int o = 64; o; o >>= 1) {
        if (t < o) st[t] += st[t + o];
        __syncthreads();
    }
    if (t == 0) y[g] = st[0] + bp2[0];
}

// ---------------- launch ----------------
extern "C" void kernel_launch(void* const* d_in, const int* in_sizes, int n_in,
                              void* d_out, int out_size)
{
    const float* X     = (const float*)d_in[0];
    const float* Xq    = (const float*)d_in[1];
    const int*   g_src = (const int*)d_in[2];
    const int*   g_dst = (const int*)d_in[3];
    const int*   q_src = (const int*)d_in[5];
    const int*   q_dst = (const int*)d_in[6];
    const float* Wg    = (const float*)d_in[8];
    const float* bg    = (const float*)d_in[9];
    const float* Wq    = (const float*)d_in[10];
    const float* bq    = (const float*)d_in[11];
    const float* betas_g = (const float*)d_in[12];
    const float* betas_q = (const float*)d_in[13];
    const float* W1r   = (const float*)d_in[14];
    const float* b1r   = (const float*)d_in[15];
    const float* W2r   = (const float*)d_in[16];
    const float* b2r   = (const float*)d_in[17];
    const float* Wp1   = (const float*)d_in[18];
    const float* bp1   = (const float*)d_in[19];
    const float* Wp2   = (const float*)d_in[20];
    const float* bp2   = (const float*)d_in[21];
    float* y = (float*)d_out;

    float *hg, *hqA, *hqB, *agg, *ssqg, *ssqqA, *ssqqB, *ssqa, *vg;
    int *csrg, *startg, *cntg, *csrq, *startq, *cntq;
    cudaGetSymbolAddress((void**)&hg, d_hg);
    cudaGetSymbolAddress((void**)&hqA, d_hqA);
    cudaGetSymbolAddress((void**)&hqB, d_hqB);
    cudaGetSymbolAddress((void**)&agg, d_agg);
    cudaGetSymbolAddress((void**)&ssqg, d_ssqg);
    cudaGetSymbolAddress((void**)&ssqqA, d_ssqqA);
    cudaGetSymbolAddress((void**)&ssqqB, d_ssqqB);
    cudaGetSymbolAddress((void**)&ssqa, d_ssqa);
    cudaGetSymbolAddress((void**)&vg, d_vg);
    cudaGetSymbolAddress((void**)&csrg, d_csrg);
    cudaGetSymbolAddress((void**)&startg, d_startg);
    cudaGetSymbolAddress((void**)&cntg, d_cntg);
    cudaGetSymbolAddress((void**)&csrq, d_csrq);
    cudaGetSymbolAddress((void**)&startq, d_startq);
    cudaGetSymbolAddress((void**)&cntq, d_cntq);

    const int SM_IN  = 2 * (128 * 72 * 2) + 2 * (64 * 136 * 2) + 256 * 4;    // 72704
    const int SM_MLP = 4 * (128 * 136 * 2) + 256 * 4;                        // 140288
    cudaFuncSetAttribute(gemm_in,   cudaFuncAttributeMaxDynamicSharedMemorySize, SM_IN);
    cudaFuncSetAttribute(mlp_fused, cudaFuncAttributeMaxDynamicSharedMemorySize, SM_MLP);

    build_csr2<NPG, EGE / NB, 16><<<NB, 512>>>(g_dst, csrg, startg, cntg);
    build_csr2<NQPG, EQE / NB, 4><<<NB, 128>>>(q_dst, csrq, startq, cntq);

    gemm_in<<<NGN / 128, 256, SM_IN>>>(X, Wg, bg, hg, ssqg);
    gemm_in<<<NQN / 128, 256, SM_IN>>>(Xq, Wq, bq, hqA, ssqqA);

    float* hq_cur = hqA;  float* ssq_cur = ssqqA;
    float* hq_nxt = hqB;  float* ssq_nxt = ssqqB;
    for (int l = 0; l < NL; l++) {
        agnn_fused<<<NQN / 8, 256>>>(hq_cur, ssq_cur, csrq, startq, cntq, q_src,
                                     betas_q, l, nullptr, 0, hq_nxt, ssq_nxt, NQN);
        pool_vg<<<NB, 128>>>(hq_nxt, W1r + (size_t)l * 2 * HD * HD + HD * HD, ssqa, vg);
        agnn_fused<<<NGN / 8, 256>>>(hg, ssqg, csrg, startg, cntg, g_src,
                                     betas_g, l, ssqa, 9, agg, nullptr, NGN);
        mlp_fused<<<NGN / 128, 256, SM_MLP>>>(agg, W1r + (size_t)l * 2 * HD * HD,
                                              W2r + (size_t)l * HD * HD,
                                              b1r + l * HD, b2r + l * HD,
                                              vg, cntg, hg, ssqg);
        float* tp = hq_cur; hq_cur = hq_nxt; hq_nxt = tp;
        float* ts = ssq_cur; ssq_cur = ssq_nxt; ssq_nxt = ts;
    }

    pool_pred<<<NB, 512>>>(hg, Wp1, bp1, Wp2, bp2, y);
}

// round 5
// speedup vs baseline: 3.8553x; 1.0769x over previous
#include <cuda_runtime.h>
#include <cuda_bf16.h>
#include <math_constants.h>
#include <cstdint>

#define NB    256
#define NPG   512
#define NGN   131072
#define EGE   1048576
#define NQPG  16
#define NQN   4096
#define EQE   32768
#define FIN   64
#define HD    128
#define NL    2

typedef __nv_bfloat16 bf16;
typedef __nv_bfloat162 bf162;

// weight layout in d_Wh/d_Wl (elements)
#define OFF_WG  0
#define OFF_WQ  8192
#define OFF_W1(l) (16384 + (l) * 32768)
#define OFF_W2(l) (16384 + (l) * 32768 + 16384)
#define WTOT    (16384 + NL * 32768)

// ---------------- device scratch ----------------
__device__ __align__(16) float d_hgA[NGN * HD];
__device__ __align__(16) float d_hgB[NGN * HD];
__device__ __align__(16) float d_hqA[NQN * HD];
__device__ __align__(16) float d_hqB[NQN * HD];
__device__ float d_ssqgA[NGN];
__device__ float d_ssqgB[NGN];
__device__ float d_ssqqA[NQN];
__device__ float d_ssqqB[NQN];
__device__ float d_ssqa[NB];
__device__ float d_vg[NB * HD];
__device__ __align__(16) bf16 d_Wh[WTOT];
__device__ __align__(16) bf16 d_Wl[WTOT];
__device__ int d_csrg[EGE];
__device__ int d_startg[NGN];
__device__ int d_cntg[NGN];
__device__ int d_csrq[EQE];
__device__ int d_startq[NQN];
__device__ int d_cntq[NQN];

// ---------------- O(E) deterministic CSR build ----------------
template<int NPGT, int EPGT, int W>
__global__ void build_csr2(const int* __restrict__ dst,
                           int* __restrict__ csr,
                           int* __restrict__ start,
                           int* __restrict__ cnt)
{
    __shared__ int hw[W][NPGT];
    __shared__ int soff[NPGT];
    const int g = blockIdx.x;
    const int nodebase = g * NPGT, edgebase = g * EPGT;
    const int tid = threadIdx.x, w = tid >> 5, lane = tid & 31;
    const int EPW = EPGT / W;

    for (int i = tid; i < W * NPGT; i += W * 32) ((int*)hw)[i] = 0;
    __syncthreads();

    const int ebase = edgebase + w * EPW;
    for (int c0 = 0; c0 < EPW; c0 += 32) {
        int d = dst[ebase + c0 + lane] - nodebase;
        unsigned mm = __match_any_sync(0xffffffffu, d);
        int leader = __ffs(mm) - 1;
        if (lane == leader) atomicAdd(&hw[w][d], __popc(mm));
    }
    __syncthreads();

    if (tid < NPGT) {
        int deg = 0;
        #pragma unroll
        for (int ww = 0; ww < W; ww++) deg += hw[ww][tid];
        cnt[nodebase + tid] = deg;
        soff[tid] = deg;
    }
    __syncthreads();
    if (tid == 0) {
        int run = 0;
        for (int i = 0; i < NPGT; i++) { int d0 = soff[i]; soff[i] = run; run += d0; }
    }
    __syncthreads();
    if (tid < NPGT) {
        int run = edgebase + soff[tid];
        start[nodebase + tid] = run;
        #pragma unroll
        for (int ww = 0; ww < W; ww++) { int t0 = hw[ww][tid]; hw[ww][tid] = run; run += t0; }
    }
    __syncthreads();

    for (int c0 = 0; c0 < EPW; c0 += 32) {
        int e = ebase + c0 + lane;
        int d = dst[e] - nodebase;
        unsigned mm = __match_any_sync(0xffffffffu, d);
        int leader = __ffs(mm) - 1;
        int r = __popc(mm & ((1u << lane) - 1));
        int basepos = 0;
        if (lane == leader) { basepos = hw[w][d]; hw[w][d] += __popc(mm); }
        basepos = __shfl_sync(0xffffffffu, basepos, leader);
        csr[basepos + r] = e;
    }
}

// ---------------- helpers ----------------
__device__ __forceinline__ uint32_t sptr(const void* p) {
    return (uint32_t)__cvta_generic_to_shared(p);
}
__device__ __forceinline__ void ldsm4(uint32_t& r0, uint32_t& r1, uint32_t& r2, uint32_t& r3, uint32_t a) {
    asm volatile("ldmatrix.sync.aligned.m8n8.x4.shared.b16 {%0,%1,%2,%3},[%4];\n"
                 : "=r"(r0), "=r"(r1), "=r"(r2), "=r"(r3) : "r"(a));
}
__device__ __forceinline__ void ldsm4t(uint32_t& r0, uint32_t& r1, uint32_t& r2, uint32_t& r3, uint32_t a) {
    asm volatile("ldmatrix.sync.aligned.m8n8.x4.trans.shared.b16 {%0,%1,%2,%3},[%4];\n"
                 : "=r"(r0), "=r"(r1), "=r"(r2), "=r"(r3) : "r"(a));
}
__device__ __forceinline__ void mma16816(float* c, const uint32_t* a, uint32_t b0, uint32_t b1) {
    asm volatile("mma.sync.aligned.m16n8k16.row.col.f32.bf16.bf16.f32 "
                 "{%0,%1,%2,%3},{%4,%5,%6,%7},{%8,%9},{%0,%1,%2,%3};\n"
                 : "+f"(c[0]), "+f"(c[1]), "+f"(c[2]), "+f"(c[3])
                 : "r"(a[0]), "r"(a[1]), "r"(a[2]), "r"(a[3]), "r"(b0), "r"(b1));
}
__device__ __forceinline__ void cpa16(void* s, const void* g) {
    asm volatile("cp.async.cg.shared.global [%0], [%1], 16;\n" :: "r"(sptr(s)), "l"(g));
}
__device__ __forceinline__ void cpcommit() { asm volatile("cp.async.commit_group;\n"); }
template<int N> __device__ __forceinline__ void cpwait() {
    asm volatile("cp.async.wait_group %0;\n" :: "n"(N));
}
__device__ __forceinline__ void split_store(bf16* hi, bf16* lo, float x, float y) {
    bf162 h = __floats2bfloat162_rn(x, y);
    bf162 l = __floats2bfloat162_rn(x - __bfloat162float(h.x), y - __bfloat162float(h.y));
    *(bf162*)hi = h;
    *(bf162*)lo = l;
}
__device__ __forceinline__ float quadsum(float v) {
    v += __shfl_xor_sync(0xffffffffu, v, 1);
    v += __shfl_xor_sync(0xffffffffu, v, 2);
    return v;
}

// ---------------- split all weights into d_Wh/d_Wl (one launch) ----------------
__global__ void split_weights(const float* __restrict__ Wg, const float* __restrict__ Wq,
                              const float* __restrict__ W1r, const float* __restrict__ W2r,
                              bf16* __restrict__ Wh, bf16* __restrict__ Wl)
{
    int i4 = blockIdx.x * blockDim.x + threadIdx.x;     // WTOT/4 threads
    int e0 = i4 * 4;
    if (e0 >= WTOT) return;
    const float* src;
    if (e0 < 8192) src = Wg + e0;
    else if (e0 < 16384) src = Wq + (e0 - 8192);
    else {
        int t = e0 - 16384;
        int l = t / 32768, r = t % 32768;
        if (r < 16384) src = W1r + (size_t)l * 32768 + r;       // W1 top (first 128 rows)
        else           src = W2r + (size_t)l * 16384 + (r - 16384);
    }
    float4 v = *(const float4*)src;
    split_store(Wh + e0,     Wl + e0,     v.x, v.y);
    split_store(Wh + e0 + 2, Wl + e0 + 2, v.z, v.w);
}

// ---------------- input projection GEMM (K=64, split-A in-kernel, pre-split W) ----------------
__global__ __launch_bounds__(256, 2) void gemm_in(
    const float* __restrict__ A, const bf16* __restrict__ Bh, const bf16* __restrict__ Bl,
    const float* __restrict__ bias, float* __restrict__ C, float* __restrict__ ssq_out)
{
    extern __shared__ __align__(16) char sm[];
    bf16* sAh = (bf16*)sm;                     // 128*72
    bf16* sAl = sAh + 128 * 72;
    bf16* sBh = sAl + 128 * 72;                // 64*136
    bf16* sBl = sBh + 64 * 136;
    float* sred = (float*)(sBl + 64 * 136);

    int tid = threadIdx.x;
    int wid = tid >> 5, lane = tid & 31;
    int warp_m = wid >> 1, warp_n = wid & 1;
    int row0 = blockIdx.x * 128;

    sred[tid] = 0.0f;

    #pragma unroll
    for (int it = 0; it < 8; it++) {
        int idx = tid + it * 256;
        int m = idx >> 4, f = (idx & 15) * 4;
        float4 v = *(const float4*)(A + (size_t)(row0 + m) * FIN + f);
        split_store(&sAh[m * 72 + f],     &sAl[m * 72 + f],     v.x, v.y);
        split_store(&sAh[m * 72 + f + 2], &sAl[m * 72 + f + 2], v.z, v.w);
    }
    #pragma unroll
    for (int it = 0; it < 4; it++) {
        int idx = tid + it * 256;
        int kk = idx >> 4, f = (idx & 15) * 8;
        *(float4*)(sBh + kk * 136 + f) = *(const float4*)(Bh + kk * 128 + f);
        *(float4*)(sBl + kk * 136 + f) = *(const float4*)(Bl + kk * 128 + f);
    }
    __syncthreads();

    float acc[2][8][4];
    #pragma unroll
    for (int i = 0; i < 2; i++)
        #pragma unroll
        for (int j = 0; j < 8; j++)
            #pragma unroll
            for (int k = 0; k < 4; k++) acc[i][j][k] = 0.0f;

    #pragma unroll
    for (int ks = 0; ks < FIN; ks += 16) {
        uint32_t ah[2][4], al[2][4];
        #pragma unroll
        for (int mt = 0; mt < 2; mt++) {
            int r = warp_m * 32 + mt * 16 + (lane & 15);
            int c = ks + (lane >> 4) * 8;
            ldsm4(ah[mt][0], ah[mt][1], ah[mt][2], ah[mt][3], sptr(sAh + r * 72 + c));
            ldsm4(al[mt][0], al[mt][1], al[mt][2], al[mt][3], sptr(sAl + r * 72 + c));
        }
        #pragma unroll
        for (int np = 0; np < 4; np++) {
            int kk = ks + (lane & 7) + ((lane >> 3) & 1) * 8;
            int cc = warp_n * 64 + np * 16 + (lane >> 4) * 8;
            uint32_t bh[4], bl[4];
            ldsm4t(bh[0], bh[1], bh[2], bh[3], sptr(sBh + kk * 136 + cc));
            ldsm4t(bl[0], bl[1], bl[2], bl[3], sptr(sBl + kk * 136 + cc));
            #pragma unroll
            for (int mt = 0; mt < 2; mt++) {
                #pragma unroll
                for (int sub = 0; sub < 2; sub++) {
                    float* c0 = acc[mt][np * 2 + sub];
                    mma16816(c0, ah[mt], bh[sub * 2], bh[sub * 2 + 1]);
                    mma16816(c0, ah[mt], bl[sub * 2], bl[sub * 2 + 1]);
                    mma16816(c0, al[mt], bh[sub * 2], bh[sub * 2 + 1]);
                }
            }
        }
    }

    #pragma unroll
    for (int mt = 0; mt < 2; mt++) {
        int rA = warp_m * 32 + mt * 16 + (lane >> 2);
        int rB = rA + 8;
        float ssA = 0.f, ssB = 0.f;
        #pragma unroll
        for (int nt = 0; nt < 8; nt++) {
            int col = warp_n * 64 + nt * 8 + (lane & 3) * 2;
            float b0 = bias[col], b1 = bias[col + 1];
            float v0 = acc[mt][nt][0] + b0;
            float v1 = acc[mt][nt][1] + b1;
            float v2 = acc[mt][nt][2] + b0;
            float v3 = acc[mt][nt][3] + b1;
            *(float2*)(C + (size_t)(row0 + rA) * 128 + col) = make_float2(v0, v1);
            *(float2*)(C + (size_t)(row0 + rB) * 128 + col) = make_float2(v2, v3);
            ssA += v0 * v0 + v1 * v1;
            ssB += v2 * v2 + v3 * v3;
        }
        ssA = quadsum(ssA); ssB = quadsum(ssB);
        if ((lane & 3) == 0) {
            sred[warp_n * 128 + rA] = ssA;
            sred[warp_n * 128 + rB] = ssB;
        }
    }
    __syncthreads();
    if (tid < 128 && ssq_out) ssq_out[row0 + tid] = sred[tid] + sred[128 + tid];
}

// ---------------- fused data-graph layer: AGNN prologue + 2-stage MLP ----------------
// Cout = relu(AGG@W1 + vg*mask + b1) @ W2 + b2 ; AGG computed in-block from hg_prev.
__global__ __launch_bounds__(256, 2) void mlp_fused(
    const float* __restrict__ h, const float* __restrict__ ssq,
    const int* __restrict__ csr, const int* __restrict__ start,
    const int* __restrict__ cnt, const int* __restrict__ src,
    const float* __restrict__ betas, int l, const float* __restrict__ ssqa,
    const bf16* __restrict__ W1h, const bf16* __restrict__ W1l,
    const bf16* __restrict__ W2h, const bf16* __restrict__ W2l,
    const float* __restrict__ bias1, const float* __restrict__ bias2,
    const float* __restrict__ vg,
    float* __restrict__ Cout, float* __restrict__ ssq_out)
{
    extern __shared__ __align__(16) char sm[];
    bf16* sAh = (bf16*)sm;                    // 128*136
    bf16* sAl = sAh + 128 * 136;
    bf16* sBh = sAl + 128 * 136;              // [2][32*136] double buffer
    bf16* sBl = sBh + 2 * 32 * 136;
    float* sred = (float*)(sBl + 2 * 32 * 136);

    int tid = threadIdx.x;
    int wid = tid >> 5, lane = tid & 31;
    int warp_m = wid >> 1, warp_n = wid & 1;
    int row0 = blockIdx.x * 128;

    sred[tid] = 0.0f;

    // ---- AGNN aggregation prologue: 16 dst nodes per warp, chunks of 8 edges ----
    float beta = betas[l];
    for (int i = 0; i < 16; i++) {
        int r = wid * 16 + i;
        int n = row0 + r;
        int c = cnt[n];
        float4 acc = make_float4(0.f, 0.f, 0.f, 0.f);
        if (c > 0) {
            float ex = ssqa[n >> 9];
            float invd = rsqrtf(ssq[n] + ex + 1e-24f);
            float4 hd = *(const float4*)(h + (size_t)n * HD + lane * 4);
            int s0 = start[n];
            float m = -CUDART_INF_F, den = 0.0f;
            for (int j0 = 0; j0 < c; j0 += 8) {
                int cc8 = min(8, c - j0);
                float4 rows[8]; float e[8];
                #pragma unroll
                for (int j = 0; j < 8; j++) {
                    if (j < cc8) {
                        int eid = csr[s0 + j0 + j];
                        int s = src[eid];
                        rows[j] = *(const float4*)(h + (size_t)s * HD + lane * 4);
                        e[j] = ssq[s];
                    } else { rows[j] = make_float4(0.f, 0.f, 0.f, 0.f); e[j] = 1.f; }
                }
                float d[8];
                #pragma unroll
                for (int j = 0; j < 8; j++)
                    d[j] = rows[j].x * hd.x + rows[j].y * hd.y + rows[j].z * hd.z + rows[j].w * hd.w;
                #pragma unroll
                for (int o = 16; o; o >>= 1)
                    #pragma unroll
                    for (int j = 0; j < 8; j++) d[j] += __shfl_xor_sync(0xffffffffu, d[j], o);
                #pragma unroll
                for (int j = 0; j < 8; j++)
                    e[j] = (j < cc8) ? beta * (d[j] + ex) * rsqrtf(e[j] + ex + 1e-24f) * invd
                                     : -CUDART_INF_F;
                float cm = e[0];
                #pragma unroll
                for (int j = 1; j < 8; j++) cm = fmaxf(cm, e[j]);
                float nm = fmaxf(m, cm);
                float corr = __expf(m - nm);
                den *= corr; acc.x *= corr; acc.y *= corr; acc.z *= corr; acc.w *= corr;
                #pragma unroll
                for (int j = 0; j < 8; j++) {
                    float p = __expf(e[j] - nm);
                    den += p;
                    acc.x += p * rows[j].x; acc.y += p * rows[j].y;
                    acc.z += p * rows[j].z; acc.w += p * rows[j].w;
                }
                m = nm;
            }
            float rr = 1.0f / fmaxf(den, 1e-24f);
            acc.x *= rr; acc.y *= rr; acc.z *= rr; acc.w *= rr;
        }
        split_store(&sAh[r * 136 + lane * 4],     &sAl[r * 136 + lane * 4],     acc.x, acc.y);
        split_store(&sAh[r * 136 + lane * 4 + 2], &sAl[r * 136 + lane * 4 + 2], acc.z, acc.w);
    }

    // ---- weight chunk loader (k=32 rows of [128x128] pre-split weight) ----
    auto load_w = [&](const bf16* Wh_, const bf16* Wl_, int kt, int buf) {
        #pragma unroll
        for (int it = 0; it < 2; it++) {
            int idx = tid + it * 256;
            int r = idx >> 4, f = (idx & 15) * 8;
            cpa16(sBh + buf * 4352 + r * 136 + f, Wh_ + (size_t)(kt * 32 + r) * 128 + f);
            cpa16(sBl + buf * 4352 + r * 136 + f, Wl_ + (size_t)(kt * 32 + r) * 128 + f);
        }
    };

    float acc4[2][8][4];
    #pragma unroll
    for (int i = 0; i < 2; i++)
        #pragma unroll
        for (int j = 0; j < 8; j++)
            #pragma unroll
            for (int k = 0; k < 4; k++) acc4[i][j][k] = 0.0f;

    auto gemm_chunk = [&](int kt, int buf) {
        #pragma unroll
        for (int ksl = 0; ksl < 32; ksl += 16) {
            int ks = kt * 32 + ksl;
            uint32_t ah[2][4], al[2][4];
            #pragma unroll
            for (int mt = 0; mt < 2; mt++) {
                int r = warp_m * 32 + mt * 16 + (lane & 15);
                int c = ks + (lane >> 4) * 8;
                ldsm4(ah[mt][0], ah[mt][1], ah[mt][2], ah[mt][3], sptr(sAh + r * 136 + c));
                ldsm4(al[mt][0], al[mt][1], al[mt][2], al[mt][3], sptr(sAl + r * 136 + c));
            }
            #pragma unroll
            for (int np = 0; np < 4; np++) {
                int kk = ksl + (lane & 7) + ((lane >> 3) & 1) * 8;
                int cc = warp_n * 64 + np * 16 + (lane >> 4) * 8;
                uint32_t bh[4], bl[4];
                ldsm4t(bh[0], bh[1], bh[2], bh[3], sptr(sBh + buf * 4352 + kk * 136 + cc));
                ldsm4t(bl[0], bl[1], bl[2], bl[3], sptr(sBl + buf * 4352 + kk * 136 + cc));
                #pragma unroll
                for (int mt = 0; mt < 2; mt++) {
                    #pragma unroll
                    for (int sub = 0; sub < 2; sub++) {
                        float* c0 = acc4[mt][np * 2 + sub];
                        mma16816(c0, ah[mt], bh[sub * 2], bh[sub * 2 + 1]);
                        mma16816(c0, ah[mt], bl[sub * 2], bl[sub * 2 + 1]);
                        mma16816(c0, al[mt], bh[sub * 2], bh[sub * 2 + 1]);
                    }
                }
            }
        }
    };

    // -------- stage 1: AGG @ W1 --------
    load_w(W1h, W1l, 0, 0); cpcommit();
    load_w(W1h, W1l, 1, 1); cpcommit();
    #pragma unroll
    for (int kt = 0; kt < 4; kt++) {
        if (kt == 3) cpwait<0>(); else cpwait<1>();
        __syncthreads();
        gemm_chunk(kt, kt & 1);
        __syncthreads();
        if (kt + 2 < 4) { load_w(W1h, W1l, kt + 2, kt & 1); cpcommit(); }
    }

    // prefetch W2 chunks while epilogue runs
    load_w(W2h, W2l, 0, 0); cpcommit();
    load_w(W2h, W2l, 1, 1); cpcommit();

    // stage-1 epilogue: bias1 + vg mask + relu -> restage into sA (split)
    #pragma unroll
    for (int mt = 0; mt < 2; mt++) {
        int rA = warp_m * 32 + mt * 16 + (lane >> 2);
        int rB = rA + 8;
        int gA = row0 + rA, gB = row0 + rB;
        float mA = (cnt[gA] > 0) ? 1.0f : 0.0f;
        float mB = (cnt[gB] > 0) ? 1.0f : 0.0f;
        const float* vA = vg + (size_t)(gA >> 9) * HD;
        const float* vB = vg + (size_t)(gB >> 9) * HD;
        #pragma unroll
        for (int nt = 0; nt < 8; nt++) {
            int col = warp_n * 64 + nt * 8 + (lane & 3) * 2;
            float b0 = bias1[col], b1 = bias1[col + 1];
            float v0 = fmaxf(acc4[mt][nt][0] + b0 + mA * vA[col],     0.f);
            float v1 = fmaxf(acc4[mt][nt][1] + b1 + mA * vA[col + 1], 0.f);
            float v2 = fmaxf(acc4[mt][nt][2] + b0 + mB * vB[col],     0.f);
            float v3 = fmaxf(acc4[mt][nt][3] + b1 + mB * vB[col + 1], 0.f);
            split_store(&sAh[rA * 136 + col], &sAl[rA * 136 + col], v0, v1);
            split_store(&sAh[rB * 136 + col], &sAl[rB * 136 + col], v2, v3);
            acc4[mt][nt][0] = 0.f; acc4[mt][nt][1] = 0.f;
            acc4[mt][nt][2] = 0.f; acc4[mt][nt][3] = 0.f;
        }
    }

    // -------- stage 2: t1 @ W2 --------
    #pragma unroll
    for (int kt = 0; kt < 4; kt++) {
        if (kt == 3) cpwait<0>(); else cpwait<1>();
        __syncthreads();
        gemm_chunk(kt, kt & 1);
        __syncthreads();
        if (kt + 2 < 4) { load_w(W2h, W2l, kt + 2, kt & 1); cpcommit(); }
    }

    // stage-2 epilogue: bias2, write Cout (next hg buffer), ssq
    #pragma unroll
    for (int mt = 0; mt < 2; mt++) {
        int rA = warp_m * 32 + mt * 16 + (lane >> 2);
        int rB = rA + 8;
        float ssA = 0.f, ssB = 0.f;
        #pragma unroll
        for (int nt = 0; nt < 8; nt++) {
            int col = warp_n * 64 + nt * 8 + (lane & 3) * 2;
            float b0 = bias2[col], b1 = bias2[col + 1];
            float v0 = acc4[mt][nt][0] + b0;
            float v1 = acc4[mt][nt][1] + b1;
            float v2 = acc4[mt][nt][2] + b0;
            float v3 = acc4[mt][nt][3] + b1;
            *(float2*)(Cout + (size_t)(row0 + rA) * 128 + col) = make_float2(v0, v1);
            *(float2*)(Cout + (size_t)(row0 + rB) * 128 + col) = make_float2(v2, v3);
            ssA += v0 * v0 + v1 * v1;
            ssB += v2 * v2 + v3 * v3;
        }
        ssA = quadsum(ssA); ssB = quadsum(ssB);
        if ((lane & 3) == 0) {
            sred[warp_n * 128 + rA] = ssA;
            sred[warp_n * 128 + rB] = ssB;
        }
    }
    __syncthreads();
    if (tid < 128) ssq_out[row0 + tid] = sred[tid] + sred[128 + tid];
}

// ---------------- query AGNN (chunked gather, warp per node) ----------------
__global__ void agnn_q(const float* __restrict__ h, const float* __restrict__ ssq,
                       const int* __restrict__ csr, const int* __restrict__ start,
                       const int* __restrict__ cnt, const int* __restrict__ src,
                       const float* __restrict__ betas, int l,
                       float* __restrict__ outf, float* __restrict__ ssq_out, int N)
{
    int n = (blockIdx.x * blockDim.x + threadIdx.x) >> 5;
    int lane = threadIdx.x & 31;
    if (n >= N) return;
    int c = cnt[n];
    float4 acc = make_float4(0.f, 0.f, 0.f, 0.f);
    if (c > 0) {
        float beta = betas[l];
        float invd = rsqrtf(ssq[n] + 1e-24f);
        float4 hd = *(const float4*)(h + (size_t)n * HD + lane * 4);
        int s0 = start[n];
        float m = -CUDART_INF_F, den = 0.0f;
        for (int j0 = 0; j0 < c; j0 += 8) {
            int cc8 = min(8, c - j0);
            float4 rows[8]; float e[8];
            #pragma unroll
            for (int j = 0; j < 8; j++) {
                if (j < cc8) {
                    int eid = csr[s0 + j0 + j];
                    int s = src[eid];
                    rows[j] = *(const float4*)(h + (size_t)s * HD + lane * 4);
                    e[j] = ssq[s];
                } else { rows[j] = make_float4(0.f, 0.f, 0.f, 0.f); e[j] = 1.f; }
            }
            float d[8];
            #pragma unroll
            for (int j = 0; j < 8; j++)
                d[j] = rows[j].x * hd.x + rows[j].y * hd.y + rows[j].z * hd.z + rows[j].w * hd.w;
            #pragma unroll
            for (int o = 16; o; o >>= 1)
                #pragma unroll
                for (int j = 0; j < 8; j++) d[j] += __shfl_xor_sync(0xffffffffu, d[j], o);
            #pragma unroll
            for (int j = 0; j < 8; j++)
                e[j] = (j < cc8) ? beta * d[j] * rsqrtf(e[j] + 1e-24f) * invd : -CUDART_INF_F;
            float cm = e[0];
            #pragma unroll
            for (int j = 1; j < 8; j++) cm = fmaxf(cm, e[j]);
            float nm = fmaxf(m, cm);
            float corr = __expf(m - nm);
            den *= corr; acc.x *= corr; acc.y *= corr; acc.z *= corr; acc.w *= corr;
            #pragma unroll
            for (int j = 0; j < 8; j++) {
                float p = __expf(e[j] - nm);
                den += p;
                acc.x += p * rows[j].x; acc.y += p * rows[j].y;
                acc.z += p * rows[j].z; acc.w += p * rows[j].w;
            }
            m = nm;
        }
        float rr = 1.0f / fmaxf(den, 1e-24f);
        acc.x *= rr; acc.y *= rr; acc.z *= rr; acc.w *= rr;
    }
    *(float4*)(outf + (size_t)n * HD + lane * 4) = acc;
    float ss = acc.x * acc.x + acc.y * acc.y + acc.z * acc.z + acc.w * acc.w;
    #pragma unroll
    for (int o = 16; o; o >>= 1) ss += __shfl_xor_sync(0xffffffffu, ss, o);
    if (lane == 0) ssq_out[n] = ss;
}

// ---------------- fused query pool: ssqa + vg = aggr@W1bot ----------------
__global__ void pool_vg(const float* __restrict__ hq, const float* __restrict__ W1bot,
                        float* __restrict__ ssqa, float* __restrict__ vgout)
{
    __shared__ float srow[HD];
    __shared__ float st[HD];
    int g = blockIdx.x, t = threadIdx.x;   // 128 threads
    float a = 0.0f;
    #pragma unroll
    for (int j = 0; j < NQPG; j++) a += hq[((size_t)g * NQPG + j) * HD + t];
    srow[t] = a;
    st[t] = a * a;
    __syncthreads();
    #pragma unroll
    for (int o = 64; o; o >>= 1) {
        if (t < o) st[t] += st[t + o];
        __syncthreads();
    }
    if (t == 0) ssqa[g] = st[0];
    float v = 0.0f;
    #pragma unroll 8
    for (int k = 0; k < HD; k++) v += srow[k] * W1bot[k * HD + t];
    vgout[g * HD + t] = v;
}

// ---------------- final pool + predictor ----------------
__global__ void pool_pred(const float* __restrict__ hg, const float* __restrict__ Wp1,
                          const float* __restrict__ bp1, const float* __restrict__ Wp2,
                          const float* __restrict__ bp2, float* __restrict__ y)
{
    __shared__ float s[512];
    __shared__ float srow[HD];
    __shared__ float st[HD];
    int g = blockIdx.x, t = threadIdx.x;   // 512 threads
    int col = t & 127, part = t >> 7;
    float acc = 0.0f;
    for (int j = part; j < NPG; j += 4)
        acc += hg[((size_t)g * NPG + j) * HD + col];
    s[t] = acc;
    __syncthreads();
    if (part == 0) srow[col] = s[col] + s[col + 128] + s[col + 256] + s[col + 384];
    __syncthreads();
    if (t < 128) {
        float a = 0.0f;
        #pragma unroll 8
        for (int k = 0; k < HD; k++) a += srow[k] * Wp1[k * HD + t];
        st[t] = fmaxf(a + bp1[t], 0.0f) * Wp2[t];
    }
    __syncthreads();
    #pragma unroll
    for (int o = 64; o; o >>= 1) {
        if (t < o) st[t] += st[t + o];
        __syncthreads();
    }
    if (t == 0) y[g] = st[0] + bp2[0];
}

// ---------------- launch ----------------
extern "C" void kernel_launch(void* const* d_in, const int* in_sizes, int n_in,
                              void* d_out, int out_size)
{
    const float* X     = (const float*)d_in[0];
    const float* Xq    = (const float*)d_in[1];
    const int*   g_src = (const int*)d_in[2];
    const int*   g_dst = (const int*)d_in[3];
    const int*   q_src = (const int*)d_in[5];
    const int*   q_dst = (const int*)d_in[6];
    const float* Wg    = (const float*)d_in[8];
    const float* bg    = (const float*)d_in[9];
    const float* Wq    = (const float*)d_in[10];
    const float* bq    = (const float*)d_in[11];
    const float* betas_g = (const float*)d_in[12];
    const float* betas_q = (const float*)d_in[13];
    const float* W1r   = (const float*)d_in[14];
    const float* b1r   = (const float*)d_in[15];
    const float* W2r   = (const float*)d_in[16];
    const float* b2r   = (const float*)d_in[17];
    const float* Wp1   = (const float*)d_in[18];
    const float* bp1   = (const float*)d_in[19];
    const float* Wp2   = (const float*)d_in[20];
    const float* bp2   = (const float*)d_in[21];
    float* y = (float*)d_out;

    float *hgA, *hgB, *hqA, *hqB, *ssqgA, *ssqgB, *ssqqA, *ssqqB, *ssqa, *vg;
    bf16 *Wh, *Wl;
    int *csrg, *startg, *cntg, *csrq, *startq, *cntq;
    cudaGetSymbolAddress((void**)&hgA, d_hgA);
    cudaGetSymbolAddress((void**)&hgB, d_hgB);
    cudaGetSymbolAddress((void**)&hqA, d_hqA);
    cudaGetSymbolAddress((void**)&hqB, d_hqB);
    cudaGetSymbolAddress((void**)&ssqgA, d_ssqgA);
    cudaGetSymbolAddress((void**)&ssqgB, d_ssqgB);
    cudaGetSymbolAddress((void**)&ssqqA, d_ssqqA);
    cudaGetSymbolAddress((void**)&ssqqB, d_ssqqB);
    cudaGetSymbolAddress((void**)&ssqa, d_ssqa);
    cudaGetSymbolAddress((void**)&vg, d_vg);
    cudaGetSymbolAddress((void**)&Wh, d_Wh);
    cudaGetSymbolAddress((void**)&Wl, d_Wl);
    cudaGetSymbolAddress((void**)&csrg, d_csrg);
    cudaGetSymbolAddress((void**)&startg, d_startg);
    cudaGetSymbolAddress((void**)&cntg, d_cntg);
    cudaGetSymbolAddress((void**)&csrq, d_csrq);
    cudaGetSymbolAddress((void**)&startq, d_startq);
    cudaGetSymbolAddress((void**)&cntq, d_cntq);

    const int SM_IN  = 2 * (128 * 72 * 2) + 2 * (64 * 136 * 2) + 256 * 4;    // 72704
    const int SM_MLP = 2 * (128 * 136 * 2) + 2 * (2 * 32 * 136 * 2) + 256 * 4; // 105472
    cudaFuncSetAttribute(gemm_in,   cudaFuncAttributeMaxDynamicSharedMemorySize, SM_IN);
    cudaFuncSetAttribute(mlp_fused, cudaFuncAttributeMaxDynamicSharedMemorySize, SM_MLP);

    build_csr2<NPG, EGE / NB, 16><<<NB, 512>>>(g_dst, csrg, startg, cntg);
    build_csr2<NQPG, EQE / NB, 4><<<NB, 128>>>(q_dst, csrq, startq, cntq);
    split_weights<<<(WTOT / 4 + 255) / 256, 256>>>(Wg, Wq, W1r, W2r, Wh, Wl);

    gemm_in<<<NGN / 128, 256, SM_IN>>>(X, Wh + OFF_WG, Wl + OFF_WG, bg, hgA, ssqgA);
    gemm_in<<<NQN / 128, 256, SM_IN>>>(Xq, Wh + OFF_WQ, Wl + OFF_WQ, bq, hqA, ssqqA);

    float* hg_cur = hgA;  float* ssqg_cur = ssqgA;
    float* hg_nxt = hgB;  float* ssqg_nxt = ssqgB;
    float* hq_cur = hqA;  float* ssqq_cur = ssqqA;
    float* hq_nxt = hqB;  float* ssqq_nxt = ssqqB;
    for (int l = 0; l < NL; l++) {
        agnn_q<<<NQN / 8, 256>>>(hq_cur, ssqq_cur, csrq, startq, cntq, q_src,
                                 betas_q, l, hq_nxt, ssqq_nxt, NQN);
        pool_vg<<<NB, 128>>>(hq_nxt, W1r + (size_t)l * 2 * HD * HD + HD * HD, ssqa, vg);
        mlp_fused<<<NGN / 128, 256, SM_MLP>>>(hg_cur, ssqg_cur, csrg, startg, cntg, g_src,
                                              betas_g, l, ssqa,
                                              Wh + OFF_W1(l), Wl + OFF_W1(l),
                                              Wh + OFF_W2(l), Wl + OFF_W2(l),
                                              b1r + l * HD, b2r + l * HD, vg,
                                              hg_nxt, ssqg_nxt);
        float* tp;
        tp = hg_cur; hg_cur = hg_nxt; hg_nxt = tp;
        tp = ssqg_cur; ssqg_cur = ssqg_nxt; ssqg_nxt = tp;
        tp = hq_cur; hq_cur = hq_nxt; hq_nxt = tp;
        tp = ssqq_cur; ssqq_cur = ssqq_nxt; ssqq_nxt = tp;
    }

    pool_pred<<<NB, 512>>>(hg_cur, Wp1, bp1, Wp2, bp2, y);
}